// round 1
// baseline (speedup 1.0000x reference)
#include <cuda_runtime.h>
#include <cuda_bf16.h>

// Problem constants (shapes are fixed by the dataset; sizes re-derived from
// in_sizes at launch for safety).
#define IN_F 256
#define HID  128
#define KC   64          // K-chunk per smem tile
#define RPB  32          // rows per block (8 warps x 4 rows)
#define MAX_NODES 50000

// Scratch for the dense intermediate support = x @ W^T + b  ([N, HID] fp32).
// Device-global (no allocation allowed in kernel_launch).
__device__ float g_support[MAX_NODES * HID];

// ---------------------------------------------------------------------------
// Kernel 1: support[n][h] = sum_k x[n][k] * W[h][k] + b[h]
// Block: 256 threads (8 warps), 32 rows. Each warp owns 4 rows; each thread
// owns cols {lane, lane+32, lane+64, lane+96} -> 16 fp32 accumulators.
// Smem: Wt tile [KC][HID] transposed with pad-1 (stride 129) so both the
// transposing STS fill (bank = (kk+c)%32, kk varies per lane) and the compute
// LDS (bank = (kk+lane)%32, lane varies) are conflict-free.
// ---------------------------------------------------------------------------
__global__ __launch_bounds__(256) void gcn_linear_kernel(
    const float* __restrict__ x,
    const float* __restrict__ W,
    const float* __restrict__ b,
    int n_nodes)
{
    __shared__ float Wt_s[KC][HID + 1];   // [kk][c], stride 129
    __shared__ float xs[RPB][KC];         // [r][kk], broadcast reads

    const int t    = threadIdx.x;
    const int lane = t & 31;
    const int w    = t >> 5;              // warp id 0..7
    const int row0 = blockIdx.x * RPB;

    float acc[4][4];                      // [r][j]
#pragma unroll
    for (int r = 0; r < 4; r++)
#pragma unroll
        for (int j = 0; j < 4; j++) acc[r][j] = 0.0f;

    for (int kc = 0; kc < IN_F; kc += KC) {
        __syncthreads();
        // Fill Wt_s: 64*128 = 8192 elems, 32 per thread. Coalesced global
        // reads (64-float rows of W), conflict-free STS via pad-1.
#pragma unroll
        for (int i = 0; i < (KC * HID) / 256; i++) {
            int idx = t + i * 256;
            int kk  = idx & (KC - 1);
            int c   = idx >> 6;
            Wt_s[kk][c] = W[c * IN_F + kc + kk];
        }
        // Fill xs: 32*64 = 2048 elems, 8 per thread, coalesced.
#pragma unroll
        for (int i = 0; i < (RPB * KC) / 256; i++) {
            int idx = t + i * 256;
            int kk  = idx & (KC - 1);
            int r   = idx >> 6;
            int row = row0 + r;
            xs[r][kk] = (row < n_nodes) ? x[(size_t)row * IN_F + kc + kk] : 0.0f;
        }
        __syncthreads();

#pragma unroll 8
        for (int kk = 0; kk < KC; kk++) {
            float wv[4];
#pragma unroll
            for (int j = 0; j < 4; j++) wv[j] = Wt_s[kk][lane + 32 * j];
#pragma unroll
            for (int r = 0; r < 4; r++) {
                float xv = xs[w * 4 + r][kk];
#pragma unroll
                for (int j = 0; j < 4; j++) acc[r][j] += xv * wv[j];
            }
        }
    }

    // Epilogue: add bias, write support (coalesced: col = lane + 32j).
#pragma unroll
    for (int j = 0; j < 4; j++) {
        float bias = __ldg(b + lane + 32 * j);
#pragma unroll
        for (int r = 0; r < 4; r++) {
            int row = row0 + w * 4 + r;
            if (row < n_nodes)
                g_support[(size_t)row * HID + lane + 32 * j] = acc[r][j] + bias;
        }
    }
}

// ---------------------------------------------------------------------------
// Kernel 2: out[row[e]][:] += val[e] * support[col[e]][:]
// One warp per edge: lane reads a float4 (16B) of the gathered support row
// (support row fits in L2: 25.6MB), 4 scalar atomicAdds into out.
// ---------------------------------------------------------------------------
__global__ __launch_bounds__(256) void gcn_scatter_kernel(
    const int*   __restrict__ adj_row,
    const int*   __restrict__ adj_col,
    const float* __restrict__ adj_val,
    float*       __restrict__ out,
    int n_edges)
{
    const int gwid = (blockIdx.x * blockDim.x + threadIdx.x) >> 5;
    const int lane = threadIdx.x & 31;
    if (gwid >= n_edges) return;

    const int   r = __ldg(adj_row + gwid);
    const int   c = __ldg(adj_col + gwid);
    const float v = __ldg(adj_val + gwid);

    const float4* sp = reinterpret_cast<const float4*>(g_support) + (size_t)c * (HID / 4);
    float4 s = sp[lane];

    float* o = out + (size_t)r * HID + lane * 4;
    atomicAdd(o + 0, v * s.x);
    atomicAdd(o + 1, v * s.y);
    atomicAdd(o + 2, v * s.z);
    atomicAdd(o + 3, v * s.w);
}

// ---------------------------------------------------------------------------
// Launch: inputs in metadata order: x, adj_row, adj_col, adj_val, W, b
// ---------------------------------------------------------------------------
extern "C" void kernel_launch(void* const* d_in, const int* in_sizes, int n_in,
                              void* d_out, int out_size)
{
    const float* x       = (const float*)d_in[0];
    const int*   adj_row = (const int*)  d_in[1];
    const int*   adj_col = (const int*)  d_in[2];
    const float* adj_val = (const float*)d_in[3];
    const float* W       = (const float*)d_in[4];
    const float* b       = (const float*)d_in[5];
    float*       out     = (float*)d_out;

    const int n_nodes = in_sizes[0] / IN_F;
    const int n_edges = in_sizes[1];

    // Zero the (poisoned) output accumulator.
    cudaMemsetAsync(d_out, 0, (size_t)out_size * sizeof(float), 0);

    // GEMM: support = x @ W^T + b
    int gemm_blocks = (n_nodes + RPB - 1) / RPB;
    gcn_linear_kernel<<<gemm_blocks, 256>>>(x, W, b, n_nodes);

    // Scatter: one warp per edge.
    int warps_needed  = n_edges;
    int scatter_blocks = (warps_needed * 32 + 255) / 256;
    gcn_scatter_kernel<<<scatter_blocks, 256>>>(adj_row, adj_col, adj_val, out, n_edges);
}

// round 2
// speedup vs baseline: 1.3243x; 1.3243x over previous
#include <cuda_runtime.h>
#include <cuda_bf16.h>

#define IN_F 256
#define HID  128
#define KC   64
#define RPB  32
#define MAX_NODES 50000
#define MAX_EDGES 800000

// Scratch (device globals; no allocation allowed in kernel_launch)
__device__ float g_support[MAX_NODES * HID];       // x @ W^T + b
__device__ int   g_cnt[MAX_NODES];                 // edges per row
__device__ int   g_row_start[MAX_NODES + 1];       // CSR offsets (exclusive scan)
__device__ int   g_cursor[MAX_NODES];              // bump cursors for bucket fill
__device__ int2  g_edge[MAX_EDGES];                // (col, val-as-int) sorted by row

// ---------------------------------------------------------------------------
// Kernel 1: support[n][h] = sum_k x[n][k] * W[h][k] + b[h]   (fp32 SIMT GEMM)
// ---------------------------------------------------------------------------
__global__ __launch_bounds__(256) void gcn_linear_kernel(
    const float* __restrict__ x,
    const float* __restrict__ W,
    const float* __restrict__ b,
    int n_nodes)
{
    __shared__ float Wt_s[KC][HID + 1];
    __shared__ float xs[RPB][KC];

    const int t    = threadIdx.x;
    const int lane = t & 31;
    const int w    = t >> 5;
    const int row0 = blockIdx.x * RPB;

    float acc[4][4];
#pragma unroll
    for (int r = 0; r < 4; r++)
#pragma unroll
        for (int j = 0; j < 4; j++) acc[r][j] = 0.0f;

    for (int kc = 0; kc < IN_F; kc += KC) {
        __syncthreads();
#pragma unroll
        for (int i = 0; i < (KC * HID) / 256; i++) {
            int idx = t + i * 256;
            int kk  = idx & (KC - 1);
            int c   = idx >> 6;
            Wt_s[kk][c] = W[c * IN_F + kc + kk];
        }
#pragma unroll
        for (int i = 0; i < (RPB * KC) / 256; i++) {
            int idx = t + i * 256;
            int kk  = idx & (KC - 1);
            int r   = idx >> 6;
            int row = row0 + r;
            xs[r][kk] = (row < n_nodes) ? x[(size_t)row * IN_F + kc + kk] : 0.0f;
        }
        __syncthreads();

#pragma unroll 8
        for (int kk = 0; kk < KC; kk++) {
            float wv[4];
#pragma unroll
            for (int j = 0; j < 4; j++) wv[j] = Wt_s[kk][lane + 32 * j];
#pragma unroll
            for (int r = 0; r < 4; r++) {
                float xv = xs[w * 4 + r][kk];
#pragma unroll
                for (int j = 0; j < 4; j++) acc[r][j] += xv * wv[j];
            }
        }
    }

#pragma unroll
    for (int j = 0; j < 4; j++) {
        float bias = __ldg(b + lane + 32 * j);
#pragma unroll
        for (int r = 0; r < 4; r++) {
            int row = row0 + w * 4 + r;
            if (row < n_nodes)
                g_support[(size_t)row * HID + lane + 32 * j] = acc[r][j] + bias;
        }
    }
}

// ---------------------------------------------------------------------------
// Kernel 2a: zero counters
// ---------------------------------------------------------------------------
__global__ void zero_cnt_kernel(int n_nodes)
{
    int i = blockIdx.x * blockDim.x + threadIdx.x;
    if (i < n_nodes) g_cnt[i] = 0;
}

// ---------------------------------------------------------------------------
// Kernel 2b: histogram edges per destination row
// ---------------------------------------------------------------------------
__global__ __launch_bounds__(256) void hist_kernel(
    const int* __restrict__ adj_row, int n_edges)
{
    int e = blockIdx.x * blockDim.x + threadIdx.x;
    if (e < n_edges) atomicAdd(&g_cnt[adj_row[e]], 1);
}

// ---------------------------------------------------------------------------
// Kernel 2c: single-block exclusive scan of g_cnt -> g_row_start, g_cursor
// 1024 threads, each owns a contiguous chunk; Hillis-Steele over partials.
// ---------------------------------------------------------------------------
__global__ __launch_bounds__(1024) void scan_kernel(int n_nodes)
{
    __shared__ int partial[1024];
    const int t = threadIdx.x;
    const int chunk = (n_nodes + 1023) / 1024;
    const int start = t * chunk;
    const int end   = min(start + chunk, n_nodes);

    int sum = 0;
    for (int i = start; i < end; i++) sum += g_cnt[i];
    partial[t] = sum;
    __syncthreads();

#pragma unroll
    for (int off = 1; off < 1024; off <<= 1) {
        int v = (t >= off) ? partial[t - off] : 0;
        __syncthreads();
        partial[t] += v;
        __syncthreads();
    }

    int base = (t > 0) ? partial[t - 1] : 0;   // exclusive prefix of this chunk
    for (int i = start; i < end; i++) {
        int c = g_cnt[i];
        g_row_start[i] = base;
        g_cursor[i]    = base;
        base += c;
    }
    if (t == 1023) g_row_start[n_nodes] = partial[1023];
}

// ---------------------------------------------------------------------------
// Kernel 2d: scatter edges into row-ordered buckets (one 8B store per edge)
// ---------------------------------------------------------------------------
__global__ __launch_bounds__(256) void fill_kernel(
    const int*   __restrict__ adj_row,
    const int*   __restrict__ adj_col,
    const float* __restrict__ adj_val,
    int n_edges)
{
    int e = blockIdx.x * blockDim.x + threadIdx.x;
    if (e >= n_edges) return;
    int r   = adj_row[e];
    int pos = atomicAdd(&g_cursor[r], 1);
    g_edge[pos] = make_int2(adj_col[e], __float_as_int(adj_val[e]));
}

// ---------------------------------------------------------------------------
// Kernel 3: warp-per-row gather-reduce. No value atomics; writes every row
// (rows with no edges get zeros), so no output memset needed.
// ---------------------------------------------------------------------------
__global__ __launch_bounds__(256) void row_gather_kernel(
    float* __restrict__ out, int n_nodes)
{
    const int row  = (blockIdx.x * blockDim.x + threadIdx.x) >> 5;
    const int lane = threadIdx.x & 31;
    if (row >= n_nodes) return;

    const int s0 = g_row_start[row];
    const int s1 = g_row_start[row + 1];

    const float4* sup4 = reinterpret_cast<const float4*>(g_support);
    float4 acc = make_float4(0.f, 0.f, 0.f, 0.f);

    int e = s0;
    // unroll-2 for MLP (two independent edge+gather chains in flight)
    for (; e + 1 < s1; e += 2) {
        int2 ev0 = g_edge[e];
        int2 ev1 = g_edge[e + 1];
        float4 s0v = sup4[(size_t)ev0.x * (HID / 4) + lane];
        float4 s1v = sup4[(size_t)ev1.x * (HID / 4) + lane];
        float v0 = __int_as_float(ev0.y);
        float v1 = __int_as_float(ev1.y);
        acc.x += v0 * s0v.x + v1 * s1v.x;
        acc.y += v0 * s0v.y + v1 * s1v.y;
        acc.z += v0 * s0v.z + v1 * s1v.z;
        acc.w += v0 * s0v.w + v1 * s1v.w;
    }
    if (e < s1) {
        int2 ev = g_edge[e];
        float4 sv = sup4[(size_t)ev.x * (HID / 4) + lane];
        float v = __int_as_float(ev.y);
        acc.x += v * sv.x; acc.y += v * sv.y;
        acc.z += v * sv.z; acc.w += v * sv.w;
    }

    reinterpret_cast<float4*>(out)[(size_t)row * (HID / 4) + lane] = acc;
}

// ---------------------------------------------------------------------------
// Launch: inputs: x, adj_row, adj_col, adj_val, W, b
// ---------------------------------------------------------------------------
extern "C" void kernel_launch(void* const* d_in, const int* in_sizes, int n_in,
                              void* d_out, int out_size)
{
    const float* x       = (const float*)d_in[0];
    const int*   adj_row = (const int*)  d_in[1];
    const int*   adj_col = (const int*)  d_in[2];
    const float* adj_val = (const float*)d_in[3];
    const float* W       = (const float*)d_in[4];
    const float* b       = (const float*)d_in[5];
    float*       out     = (float*)d_out;

    const int n_nodes = in_sizes[0] / IN_F;
    const int n_edges = in_sizes[1];

    // GEMM leg (independent of binning; runs first in stream)
    gcn_linear_kernel<<<(n_nodes + RPB - 1) / RPB, 256>>>(x, W, b, n_nodes);

    // CSR binning
    zero_cnt_kernel<<<(n_nodes + 255) / 256, 256>>>(n_nodes);
    hist_kernel<<<(n_edges + 255) / 256, 256>>>(adj_row, n_edges);
    scan_kernel<<<1, 1024>>>(n_nodes);
    fill_kernel<<<(n_edges + 255) / 256, 256>>>(adj_row, adj_col, adj_val, n_edges);

    // Warp-per-row gather-reduce (writes every output row; no memset needed)
    row_gather_kernel<<<(n_nodes * 32 + 255) / 256, 256>>>(out, n_nodes);
}

// round 3
// speedup vs baseline: 1.8587x; 1.4035x over previous
#include <cuda_runtime.h>
#include <cuda_bf16.h>

#define IN_F 256
#define HID  128
#define KC   64
#define RPB  32
#define MAX_NODES 50000
#define MAX_EDGES 800000
#define SCAN_B   256                     // elements per scan block
#define MAX_SB   256                     // max scan blocks (196 used)

// Scratch (device globals; no allocation allowed in kernel_launch)
__device__ float g_support[MAX_NODES * HID];
__device__ int   g_cnt[MAX_NODES];
__device__ int   g_row_start[MAX_NODES + 1];
__device__ int   g_cursor[MAX_NODES];
__device__ int2  g_edge[MAX_EDGES];
__device__ int   g_bsum[MAX_SB];         // per-block sums
__device__ int   g_boff[MAX_SB];         // per-block exclusive offsets

// ---------------------------------------------------------------------------
// Kernel 1: support = x @ W^T + b   (fp32 SIMT GEMM, near FFMA floor)
// ---------------------------------------------------------------------------
__global__ __launch_bounds__(256) void gcn_linear_kernel(
    const float* __restrict__ x,
    const float* __restrict__ W,
    const float* __restrict__ b,
    int n_nodes)
{
    __shared__ float Wt_s[KC][HID + 1];
    __shared__ float xs[RPB][KC];

    const int t    = threadIdx.x;
    const int lane = t & 31;
    const int w    = t >> 5;
    const int row0 = blockIdx.x * RPB;

    float acc[4][4];
#pragma unroll
    for (int r = 0; r < 4; r++)
#pragma unroll
        for (int j = 0; j < 4; j++) acc[r][j] = 0.0f;

    for (int kc = 0; kc < IN_F; kc += KC) {
        __syncthreads();
#pragma unroll
        for (int i = 0; i < (KC * HID) / 256; i++) {
            int idx = t + i * 256;
            int kk  = idx & (KC - 1);
            int c   = idx >> 6;
            Wt_s[kk][c] = W[c * IN_F + kc + kk];
        }
#pragma unroll
        for (int i = 0; i < (RPB * KC) / 256; i++) {
            int idx = t + i * 256;
            int kk  = idx & (KC - 1);
            int r   = idx >> 6;
            int row = row0 + r;
            xs[r][kk] = (row < n_nodes) ? x[(size_t)row * IN_F + kc + kk] : 0.0f;
        }
        __syncthreads();

#pragma unroll 8
        for (int kk = 0; kk < KC; kk++) {
            float wv[4];
#pragma unroll
            for (int j = 0; j < 4; j++) wv[j] = Wt_s[kk][lane + 32 * j];
#pragma unroll
            for (int r = 0; r < 4; r++) {
                float xv = xs[w * 4 + r][kk];
#pragma unroll
                for (int j = 0; j < 4; j++) acc[r][j] += xv * wv[j];
            }
        }
    }

#pragma unroll
    for (int j = 0; j < 4; j++) {
        float bias = __ldg(b + lane + 32 * j);
#pragma unroll
        for (int r = 0; r < 4; r++) {
            int row = row0 + w * 4 + r;
            if (row < n_nodes)
                g_support[(size_t)row * HID + lane + 32 * j] = acc[r][j] + bias;
        }
    }
}

// ---------------------------------------------------------------------------
// Binning: zero counters, histogram rows
// ---------------------------------------------------------------------------
__global__ void zero_cnt_kernel(int n_nodes)
{
    int i = blockIdx.x * blockDim.x + threadIdx.x;
    if (i < n_nodes) g_cnt[i] = 0;
}

__global__ __launch_bounds__(256) void hist_kernel(
    const int* __restrict__ adj_row, int n_edges)
{
    int e = blockIdx.x * blockDim.x + threadIdx.x;
    if (e < n_edges) atomicAdd(&g_cnt[adj_row[e]], 1);
}

// ---------------------------------------------------------------------------
// 3-phase parallel exclusive scan of g_cnt (replaces 78us single-block scan)
// Phase A: per-block reduce (256 elems/block) -> g_bsum
// ---------------------------------------------------------------------------
__global__ __launch_bounds__(SCAN_B) void scan_a_kernel(int n_nodes)
{
    __shared__ int sm[SCAN_B / 32];
    const int t   = threadIdx.x;
    const int idx = blockIdx.x * SCAN_B + t;
    int v = (idx < n_nodes) ? g_cnt[idx] : 0;
#pragma unroll
    for (int o = 16; o > 0; o >>= 1) v += __shfl_down_sync(0xffffffffu, v, o);
    if ((t & 31) == 0) sm[t >> 5] = v;
    __syncthreads();
    if (t < 32) {
        int s = (t < SCAN_B / 32) ? sm[t] : 0;
#pragma unroll
        for (int o = 4; o > 0; o >>= 1) s += __shfl_down_sync(0xffffffffu, s, o);
        if (t == 0) g_bsum[blockIdx.x] = s;
    }
}

// Phase B: single block scans the (<=256) block sums -> exclusive g_boff, total
__global__ __launch_bounds__(SCAN_B) void scan_b_kernel(int n_blocks, int n_nodes)
{
    __shared__ int sm[SCAN_B];
    const int t = threadIdx.x;
    int v = (t < n_blocks) ? g_bsum[t] : 0;
    sm[t] = v;
    __syncthreads();
#pragma unroll
    for (int o = 1; o < SCAN_B; o <<= 1) {
        int u = (t >= o) ? sm[t - o] : 0;
        __syncthreads();
        sm[t] += u;
        __syncthreads();
    }
    if (t < n_blocks) g_boff[t] = sm[t] - v;        // exclusive
    if (t == n_blocks - 1) g_row_start[n_nodes] = sm[t];
}

// Phase C: block-local exclusive scan + block offset -> g_row_start, g_cursor
__global__ __launch_bounds__(SCAN_B) void scan_c_kernel(int n_nodes)
{
    __shared__ int sm[SCAN_B];
    const int t   = threadIdx.x;
    const int idx = blockIdx.x * SCAN_B + t;
    int v = (idx < n_nodes) ? g_cnt[idx] : 0;
    sm[t] = v;
    __syncthreads();
#pragma unroll
    for (int o = 1; o < SCAN_B; o <<= 1) {
        int u = (t >= o) ? sm[t - o] : 0;
        __syncthreads();
        sm[t] += u;
        __syncthreads();
    }
    if (idx < n_nodes) {
        int excl = g_boff[blockIdx.x] + sm[t] - v;
        g_row_start[idx] = excl;
        g_cursor[idx]    = excl;
    }
}

// ---------------------------------------------------------------------------
// Fill buckets: one 8B store + one counter atomic per edge
// ---------------------------------------------------------------------------
__global__ __launch_bounds__(256) void fill_kernel(
    const int*   __restrict__ adj_row,
    const int*   __restrict__ adj_col,
    const float* __restrict__ adj_val,
    int n_edges)
{
    int e = blockIdx.x * blockDim.x + threadIdx.x;
    if (e >= n_edges) return;
    int r   = adj_row[e];
    int pos = atomicAdd(&g_cursor[r], 1);
    g_edge[pos] = make_int2(adj_col[e], __float_as_int(adj_val[e]));
}

// ---------------------------------------------------------------------------
// Warp-per-row gather-reduce; writes every row (no value atomics, no memset)
// ---------------------------------------------------------------------------
__global__ __launch_bounds__(256) void row_gather_kernel(
    float* __restrict__ out, int n_nodes)
{
    const int row  = (blockIdx.x * blockDim.x + threadIdx.x) >> 5;
    const int lane = threadIdx.x & 31;
    if (row >= n_nodes) return;

    const int s0 = g_row_start[row];
    const int s1 = g_row_start[row + 1];

    const float4* sup4 = reinterpret_cast<const float4*>(g_support);
    float4 acc = make_float4(0.f, 0.f, 0.f, 0.f);

    int e = s0;
    for (; e + 1 < s1; e += 2) {
        int2 ev0 = g_edge[e];
        int2 ev1 = g_edge[e + 1];
        float4 s0v = sup4[(size_t)ev0.x * (HID / 4) + lane];
        float4 s1v = sup4[(size_t)ev1.x * (HID / 4) + lane];
        float v0 = __int_as_float(ev0.y);
        float v1 = __int_as_float(ev1.y);
        acc.x += v0 * s0v.x + v1 * s1v.x;
        acc.y += v0 * s0v.y + v1 * s1v.y;
        acc.z += v0 * s0v.z + v1 * s1v.z;
        acc.w += v0 * s0v.w + v1 * s1v.w;
    }
    if (e < s1) {
        int2 ev = g_edge[e];
        float4 sv = sup4[(size_t)ev.x * (HID / 4) + lane];
        float v = __int_as_float(ev.y);
        acc.x += v * sv.x; acc.y += v * sv.y;
        acc.z += v * sv.z; acc.w += v * sv.w;
    }

    reinterpret_cast<float4*>(out)[(size_t)row * (HID / 4) + lane] = acc;
}

// ---------------------------------------------------------------------------
// Launch: inputs: x, adj_row, adj_col, adj_val, W, b
// ---------------------------------------------------------------------------
extern "C" void kernel_launch(void* const* d_in, const int* in_sizes, int n_in,
                              void* d_out, int out_size)
{
    const float* x       = (const float*)d_in[0];
    const int*   adj_row = (const int*)  d_in[1];
    const int*   adj_col = (const int*)  d_in[2];
    const float* adj_val = (const float*)d_in[3];
    const float* W       = (const float*)d_in[4];
    const float* b       = (const float*)d_in[5];
    float*       out     = (float*)d_out;

    const int n_nodes = in_sizes[0] / IN_F;
    const int n_edges = in_sizes[1];
    const int n_sb    = (n_nodes + SCAN_B - 1) / SCAN_B;   // 196

    gcn_linear_kernel<<<(n_nodes + RPB - 1) / RPB, 256>>>(x, W, b, n_nodes);

    zero_cnt_kernel<<<(n_nodes + 255) / 256, 256>>>(n_nodes);
    hist_kernel<<<(n_edges + 255) / 256, 256>>>(adj_row, n_edges);
    scan_a_kernel<<<n_sb, SCAN_B>>>(n_nodes);
    scan_b_kernel<<<1, SCAN_B>>>(n_sb, n_nodes);
    scan_c_kernel<<<n_sb, SCAN_B>>>(n_nodes);
    fill_kernel<<<(n_edges + 255) / 256, 256>>>(adj_row, adj_col, adj_val, n_edges);

    row_gather_kernel<<<(n_nodes * 32 + 255) / 256, 256>>>(out, n_nodes);
}

// round 5
// speedup vs baseline: 2.9259x; 1.5741x over previous
#include <cuda_runtime.h>
#include <cuda_bf16.h>
#include <cstdint>

#define IN_F 256
#define HID  128
#define TILE_M 128
#define KC   64
#define MAX_NODES 50000
#define MAX_EDGES 800000
#define SCAN_B   256
#define MAX_SB   256

// Scratch (device globals; no allocation allowed in kernel_launch)
__device__ float g_support[MAX_NODES * HID];
__device__ int   g_cnt[MAX_NODES];
__device__ int   g_row_start[MAX_NODES + 1];
__device__ int   g_cursor[MAX_NODES];
__device__ int2  g_edge[MAX_EDGES];
__device__ int   g_bsum[MAX_SB];
__device__ int   g_boff[MAX_SB];

// ---------------------------------------------------------------------------
// Helpers (all plain sm_80-era PTX; no arch-'a' gated instructions)
// ---------------------------------------------------------------------------
__device__ __forceinline__ uint32_t smem_to_u32(const void* p) {
    uint32_t a;
    asm("{ .reg .u64 t; cvta.to.shared.u64 t, %1; cvt.u32.u64 %0, t; }"
        : "=r"(a) : "l"(p));
    return a;
}

__device__ __forceinline__ void ldsm4(uint32_t* r, uint32_t addr) {
    asm volatile("ldmatrix.sync.aligned.m8n8.x4.shared.b16 {%0,%1,%2,%3}, [%4];"
        : "=r"(r[0]), "=r"(r[1]), "=r"(r[2]), "=r"(r[3]) : "r"(addr));
}

__device__ __forceinline__ void mma16816(float* c, const uint32_t* a, const uint32_t* b) {
    asm volatile("mma.sync.aligned.m16n8k16.row.col.f32.bf16.bf16.f32 "
        "{%0,%1,%2,%3}, {%4,%5,%6,%7}, {%8,%9}, {%0,%1,%2,%3};"
        : "+f"(c[0]), "+f"(c[1]), "+f"(c[2]), "+f"(c[3])
        : "r"(a[0]), "r"(a[1]), "r"(a[2]), "r"(a[3]), "r"(b[0]), "r"(b[1]));
}

__device__ __forceinline__ uint32_t pk_bf16(float a, float b) {
    __nv_bfloat162 p = __floats2bfloat162_rn(a, b);
    return reinterpret_cast<uint32_t&>(p);
}

// smem tile layout: 128 rows x 64 bf16 = 128B per row; SW128 xor swizzle:
// addr(row, cbyte) = row*128 + (cbyte ^ ((row&7)<<4)), cbyte multiple of 16.
#define OFF_AH 0
#define OFF_AL 16384
#define OFF_BH 32768
#define OFF_BL 49152
#define GEMM_SMEM 65536

// ---------------------------------------------------------------------------
// Kernel 1: support = x @ W^T + b via mma.sync bf16-split (3-pass).
// CTA: 128 rows x 128 cols, 8 warps (4x2), warp tile 32x64.
// ---------------------------------------------------------------------------
__global__ __launch_bounds__(256, 2) void gcn_linear_mma_kernel(
    const float* __restrict__ x,
    const float* __restrict__ W,
    const float* __restrict__ b,
    int n_nodes)
{
    extern __shared__ char smem[];
    const uint32_t sb = smem_to_u32(smem);
    const int t    = threadIdx.x;
    const int wid  = t >> 5;
    const int lane = t & 31;
    const int row0 = blockIdx.x * TILE_M;

    // Fill-phase role: thread owns tile row fr, k-half fh (32 floats each).
    const int fr = t & 127;
    const int fh = t >> 7;
    const uint32_t frow_base = fr * 128;
    const uint32_t fxorm = (fr & 7) << 4;
    const bool a_valid = (row0 + fr) < n_nodes;

    // Compute-phase role: warp (wm rows, wn cols)
    const int wm = (wid & 3) * 32;
    const int wn = (wid >> 2) * 64;

    float acc[2][8][4];
#pragma unroll
    for (int mt = 0; mt < 2; mt++)
#pragma unroll
        for (int nt = 0; nt < 8; nt++)
#pragma unroll
            for (int j = 0; j < 4; j++) acc[mt][nt][j] = 0.0f;

    for (int c = 0; c < IN_F / KC; c++) {
        __syncthreads();
        // ---- fill Ah/Al from x, Bh/Bl from W (split hi/lo bf16) ----
        const float* xs = x + (size_t)(row0 + fr) * IN_F + c * KC + fh * 32;
        const float* ws = W + (size_t)fr * IN_F + c * KC + fh * 32;
#pragma unroll
        for (int m = 0; m < 4; m++) {               // 8 floats -> one 16B hi + 16B lo
            float4 va = a_valid ? *(const float4*)(xs + m * 8)
                                : make_float4(0.f, 0.f, 0.f, 0.f);
            float4 vb = a_valid ? *(const float4*)(xs + m * 8 + 4)
                                : make_float4(0.f, 0.f, 0.f, 0.f);
            uint32_t off = frow_base + ((uint32_t)(fh * 64 + m * 16) ^ fxorm);
            // hi
            float hax = __bfloat162float(__float2bfloat16_rn(va.x));
            float hay = __bfloat162float(__float2bfloat16_rn(va.y));
            float haz = __bfloat162float(__float2bfloat16_rn(va.z));
            float haw = __bfloat162float(__float2bfloat16_rn(va.w));
            float hbx = __bfloat162float(__float2bfloat16_rn(vb.x));
            float hby = __bfloat162float(__float2bfloat16_rn(vb.y));
            float hbz = __bfloat162float(__float2bfloat16_rn(vb.z));
            float hbw = __bfloat162float(__float2bfloat16_rn(vb.w));
            uint4 hi = make_uint4(pk_bf16(hax, hay), pk_bf16(haz, haw),
                                  pk_bf16(hbx, hby), pk_bf16(hbz, hbw));
            uint4 lo = make_uint4(pk_bf16(va.x - hax, va.y - hay),
                                  pk_bf16(va.z - haz, va.w - haw),
                                  pk_bf16(vb.x - hbx, vb.y - hby),
                                  pk_bf16(vb.z - hbz, vb.w - hbw));
            *(uint4*)(smem + OFF_AH + off) = hi;
            *(uint4*)(smem + OFF_AL + off) = lo;

            float4 wa = *(const float4*)(ws + m * 8);
            float4 wb = *(const float4*)(ws + m * 8 + 4);
            float gax = __bfloat162float(__float2bfloat16_rn(wa.x));
            float gay = __bfloat162float(__float2bfloat16_rn(wa.y));
            float gaz = __bfloat162float(__float2bfloat16_rn(wa.z));
            float gaw = __bfloat162float(__float2bfloat16_rn(wa.w));
            float gbx = __bfloat162float(__float2bfloat16_rn(wb.x));
            float gby = __bfloat162float(__float2bfloat16_rn(wb.y));
            float gbz = __bfloat162float(__float2bfloat16_rn(wb.z));
            float gbw = __bfloat162float(__float2bfloat16_rn(wb.w));
            uint4 whi = make_uint4(pk_bf16(gax, gay), pk_bf16(gaz, gaw),
                                   pk_bf16(gbx, gby), pk_bf16(gbz, gbw));
            uint4 wlo = make_uint4(pk_bf16(wa.x - gax, wa.y - gay),
                                   pk_bf16(wa.z - gaz, wa.w - gaw),
                                   pk_bf16(wb.x - gbx, wb.y - gby),
                                   pk_bf16(wb.z - gbz, wb.w - gbw));
            *(uint4*)(smem + OFF_BH + off) = whi;
            *(uint4*)(smem + OFF_BL + off) = wlo;
        }
        __syncthreads();

        // ---- compute: 4 K16 steps ----
#pragma unroll
        for (int ks = 0; ks < 4; ks++) {
            uint32_t ah[2][4], al[2][4];
#pragma unroll
            for (int mt = 0; mt < 2; mt++) {
                int row = wm + mt * 16 + (lane & 15);
                uint32_t cb = (uint32_t)(ks * 32 + ((lane >> 4) << 4));
                uint32_t off = row * 128 + (cb ^ ((row & 7) << 4));
                ldsm4(ah[mt], sb + OFF_AH + off);
                ldsm4(al[mt], sb + OFF_AL + off);
            }
#pragma unroll
            for (int ng = 0; ng < 4; ng++) {
                int nrow = wn + ng * 16 + (lane & 7) + ((lane >> 4) << 3);
                uint32_t cb = (uint32_t)(ks * 32 + (((lane >> 3) & 1) << 4));
                uint32_t off = nrow * 128 + (cb ^ ((nrow & 7) << 4));
                uint32_t bh[4], bl[4];
                ldsm4(bh, sb + OFF_BH + off);
                ldsm4(bl, sb + OFF_BL + off);
#pragma unroll
                for (int sub = 0; sub < 2; sub++) {
                    int nt = ng * 2 + sub;
#pragma unroll
                    for (int mt = 0; mt < 2; mt++) {
                        mma16816(acc[mt][nt], ah[mt], bh + sub * 2);
                        mma16816(acc[mt][nt], ah[mt], bl + sub * 2);
                        mma16816(acc[mt][nt], al[mt], bh + sub * 2);
                    }
                }
            }
        }
    }

    // ---- epilogue: bias + store (c-frag: rows lane/4, lane/4+8; cols 2*(lane&3)) ----
#pragma unroll
    for (int nt = 0; nt < 8; nt++) {
        int col = wn + nt * 8 + 2 * (lane & 3);
        float2 bb = *(const float2*)(b + col);
#pragma unroll
        for (int mt = 0; mt < 2; mt++) {
            int r0g = row0 + wm + mt * 16 + (lane >> 2);
            if (r0g < n_nodes) {
                float2 v0 = make_float2(acc[mt][nt][0] + bb.x, acc[mt][nt][1] + bb.y);
                *(float2*)(g_support + (size_t)r0g * HID + col) = v0;
            }
            int r1g = r0g + 8;
            if (r1g < n_nodes) {
                float2 v1 = make_float2(acc[mt][nt][2] + bb.x, acc[mt][nt][3] + bb.y);
                *(float2*)(g_support + (size_t)r1g * HID + col) = v1;
            }
        }
    }
}

// ---------------------------------------------------------------------------
// Binning: zero counters, histogram rows
// ---------------------------------------------------------------------------
__global__ void zero_cnt_kernel(int n_nodes)
{
    int i = blockIdx.x * blockDim.x + threadIdx.x;
    if (i < n_nodes) g_cnt[i] = 0;
}

__global__ __launch_bounds__(256) void hist_kernel(
    const int* __restrict__ adj_row, int n_edges)
{
    int e = blockIdx.x * blockDim.x + threadIdx.x;
    if (e < n_edges) atomicAdd(&g_cnt[adj_row[e]], 1);
}

// 3-phase parallel exclusive scan of g_cnt
__global__ __launch_bounds__(SCAN_B) void scan_a_kernel(int n_nodes)
{
    __shared__ int sm[SCAN_B / 32];
    const int t   = threadIdx.x;
    const int idx = blockIdx.x * SCAN_B + t;
    int v = (idx < n_nodes) ? g_cnt[idx] : 0;
#pragma unroll
    for (int o = 16; o > 0; o >>= 1) v += __shfl_down_sync(0xffffffffu, v, o);
    if ((t & 31) == 0) sm[t >> 5] = v;
    __syncthreads();
    if (t < 32) {
        int s = (t < SCAN_B / 32) ? sm[t] : 0;
#pragma unroll
        for (int o = 4; o > 0; o >>= 1) s += __shfl_down_sync(0xffffffffu, s, o);
        if (t == 0) g_bsum[blockIdx.x] = s;
    }
}

__global__ __launch_bounds__(SCAN_B) void scan_b_kernel(int n_blocks, int n_nodes)
{
    __shared__ int sm[SCAN_B];
    const int t = threadIdx.x;
    int v = (t < n_blocks) ? g_bsum[t] : 0;
    sm[t] = v;
    __syncthreads();
#pragma unroll
    for (int o = 1; o < SCAN_B; o <<= 1) {
        int u = (t >= o) ? sm[t - o] : 0;
        __syncthreads();
        sm[t] += u;
        __syncthreads();
    }
    if (t < n_blocks) g_boff[t] = sm[t] - v;
    if (t == n_blocks - 1) g_row_start[n_nodes] = sm[t];
}

__global__ __launch_bounds__(SCAN_B) void scan_c_kernel(int n_nodes)
{
    __shared__ int sm[SCAN_B];
    const int t   = threadIdx.x;
    const int idx = blockIdx.x * SCAN_B + t;
    int v = (idx < n_nodes) ? g_cnt[idx] : 0;
    sm[t] = v;
    __syncthreads();
#pragma unroll
    for (int o = 1; o < SCAN_B; o <<= 1) {
        int u = (t >= o) ? sm[t - o] : 0;
        __syncthreads();
        sm[t] += u;
        __syncthreads();
    }
    if (idx < n_nodes) {
        int excl = g_boff[blockIdx.x] + sm[t] - v;
        g_row_start[idx] = excl;
        g_cursor[idx]    = excl;
    }
}

// Fill buckets: one 8B store + one counter atomic per edge
__global__ __launch_bounds__(256) void fill_kernel(
    const int*   __restrict__ adj_row,
    const int*   __restrict__ adj_col,
    const float* __restrict__ adj_val,
    int n_edges)
{
    int e = blockIdx.x * blockDim.x + threadIdx.x;
    if (e >= n_edges) return;
    int r   = adj_row[e];
    int pos = atomicAdd(&g_cursor[r], 1);
    g_edge[pos] = make_int2(adj_col[e], __float_as_int(adj_val[e]));
}

// Warp-per-row gather-reduce; writes every row (no value atomics, no memset)
__global__ __launch_bounds__(256) void row_gather_kernel(
    float* __restrict__ out, int n_nodes)
{
    const int row  = (blockIdx.x * blockDim.x + threadIdx.x) >> 5;
    const int lane = threadIdx.x & 31;
    if (row >= n_nodes) return;

    const int s0 = g_row_start[row];
    const int s1 = g_row_start[row + 1];

    const float4* sup4 = reinterpret_cast<const float4*>(g_support);
    float4 acc = make_float4(0.f, 0.f, 0.f, 0.f);

    int e = s0;
    for (; e + 1 < s1; e += 2) {
        int2 ev0 = g_edge[e];
        int2 ev1 = g_edge[e + 1];
        float4 s0v = sup4[(size_t)ev0.x * (HID / 4) + lane];
        float4 s1v = sup4[(size_t)ev1.x * (HID / 4) + lane];
        float v0 = __int_as_float(ev0.y);
        float v1 = __int_as_float(ev1.y);
        acc.x += v0 * s0v.x + v1 * s1v.x;
        acc.y += v0 * s0v.y + v1 * s1v.y;
        acc.z += v0 * s0v.z + v1 * s1v.z;
        acc.w += v0 * s0v.w + v1 * s1v.w;
    }
    if (e < s1) {
        int2 ev = g_edge[e];
        float4 sv = sup4[(size_t)ev.x * (HID / 4) + lane];
        float v = __int_as_float(ev.y);
        acc.x += v * sv.x; acc.y += v * sv.y;
        acc.z += v * sv.z; acc.w += v * sv.w;
    }

    reinterpret_cast<float4*>(out)[(size_t)row * (HID / 4) + lane] = acc;
}

// ---------------------------------------------------------------------------
// Launch: inputs: x, adj_row, adj_col, adj_val, W, b
// ---------------------------------------------------------------------------
extern "C" void kernel_launch(void* const* d_in, const int* in_sizes, int n_in,
                              void* d_out, int out_size)
{
    const float* x       = (const float*)d_in[0];
    const int*   adj_row = (const int*)  d_in[1];
    const int*   adj_col = (const int*)  d_in[2];
    const float* adj_val = (const float*)d_in[3];
    const float* W       = (const float*)d_in[4];
    const float* b       = (const float*)d_in[5];
    float*       out     = (float*)d_out;

    const int n_nodes = in_sizes[0] / IN_F;
    const int n_edges = in_sizes[1];
    const int n_sb    = (n_nodes + SCAN_B - 1) / SCAN_B;

    cudaFuncSetAttribute(gcn_linear_mma_kernel,
                         cudaFuncAttributeMaxDynamicSharedMemorySize, GEMM_SMEM);

    gcn_linear_mma_kernel<<<(n_nodes + TILE_M - 1) / TILE_M, 256, GEMM_SMEM>>>(
        x, W, b, n_nodes);

    zero_cnt_kernel<<<(n_nodes + 255) / 256, 256>>>(n_nodes);
    hist_kernel<<<(n_edges + 255) / 256, 256>>>(adj_row, n_edges);
    scan_a_kernel<<<n_sb, SCAN_B>>>(n_nodes);
    scan_b_kernel<<<1, SCAN_B>>>(n_sb, n_nodes);
    scan_c_kernel<<<n_sb, SCAN_B>>>(n_nodes);
    fill_kernel<<<(n_edges + 255) / 256, 256>>>(adj_row, adj_col, adj_val, n_edges);

    row_gather_kernel<<<(n_nodes * 32 + 255) / 256, 256>>>(out, n_nodes);
}

// round 6
// speedup vs baseline: 3.2016x; 1.0942x over previous
#include <cuda_runtime.h>
#include <cuda_bf16.h>
#include <cstdint>

#define IN_F 256
#define HID  128
#define TILE_M 128
#define KC   64
#define MAX_NODES 50000
#define MAX_EDGES 800000
#define SCAN_B   256
#define MAX_SB   256
#define HIST_BLOCKS 296

// Scratch (device globals; no allocation allowed in kernel_launch).
// INVARIANT: g_cnt is all-zero at kernel_launch entry; scan_c re-zeroes it.
__device__ float g_support[MAX_NODES * HID];
__device__ int   g_cnt[MAX_NODES];
__device__ int   g_row_start[MAX_NODES + 1];
__device__ int   g_cursor[MAX_NODES];
__device__ int2  g_edge[MAX_EDGES];
__device__ int   g_bsum[MAX_SB];

// ---------------------------------------------------------------------------
// Helpers (plain sm_80-era PTX; nothing arch-'a' gated)
// ---------------------------------------------------------------------------
__device__ __forceinline__ uint32_t smem_to_u32(const void* p) {
    uint32_t a;
    asm("{ .reg .u64 t; cvta.to.shared.u64 t, %1; cvt.u32.u64 %0, t; }"
        : "=r"(a) : "l"(p));
    return a;
}

__device__ __forceinline__ void ldsm4(uint32_t* r, uint32_t addr) {
    asm volatile("ldmatrix.sync.aligned.m8n8.x4.shared.b16 {%0,%1,%2,%3}, [%4];"
        : "=r"(r[0]), "=r"(r[1]), "=r"(r[2]), "=r"(r[3]) : "r"(addr));
}

__device__ __forceinline__ void mma16816(float* c, const uint32_t* a, const uint32_t* b) {
    asm volatile("mma.sync.aligned.m16n8k16.row.col.f32.bf16.bf16.f32 "
        "{%0,%1,%2,%3}, {%4,%5,%6,%7}, {%8,%9}, {%0,%1,%2,%3};"
        : "+f"(c[0]), "+f"(c[1]), "+f"(c[2]), "+f"(c[3])
        : "r"(a[0]), "r"(a[1]), "r"(a[2]), "r"(a[3]), "r"(b[0]), "r"(b[1]));
}

__device__ __forceinline__ uint32_t pk_bf16(float a, float b) {
    __nv_bfloat162 p = __floats2bfloat162_rn(a, b);
    return reinterpret_cast<uint32_t&>(p);
}

// smem tile layout: 128 rows x 64 bf16 = 128B per row; SW128 xor swizzle.
#define OFF_AH 0
#define OFF_AL 16384
#define OFF_BH 32768
#define OFF_BL 49152
#define GEMM_SMEM 65536

// ---------------------------------------------------------------------------
// Fat kernel 1: blocks [0, gemm_blocks) -> GEMM (support = x@W^T + b, bf16
// split 3-pass mma.sync).  Blocks [gemm_blocks, ...) -> edge histogram
// (grid-stride atomics into g_cnt; relies on the zero-invariant).
// ---------------------------------------------------------------------------
__global__ __launch_bounds__(256, 2) void gemm_hist_kernel(
    const float* __restrict__ x,
    const float* __restrict__ W,
    const float* __restrict__ b,
    const int*   __restrict__ adj_row,
    int n_nodes, int n_edges, int gemm_blocks)
{
    if (blockIdx.x >= gemm_blocks) {
        // ---------------- histogram part ----------------
        int stride = (gridDim.x - gemm_blocks) * blockDim.x;
        for (int e = (blockIdx.x - gemm_blocks) * blockDim.x + threadIdx.x;
             e < n_edges; e += stride)
            atomicAdd(&g_cnt[adj_row[e]], 1);
        return;
    }

    // ---------------- GEMM part ----------------
    extern __shared__ char smem[];
    const uint32_t sb = smem_to_u32(smem);
    const int t    = threadIdx.x;
    const int wid  = t >> 5;
    const int lane = t & 31;
    const int row0 = blockIdx.x * TILE_M;

    const int fr = t & 127;
    const int fh = t >> 7;
    const uint32_t frow_base = fr * 128;
    const uint32_t fxorm = (fr & 7) << 4;
    const bool a_valid = (row0 + fr) < n_nodes;

    const int wm = (wid & 3) * 32;
    const int wn = (wid >> 2) * 64;

    float acc[2][8][4];
#pragma unroll
    for (int mt = 0; mt < 2; mt++)
#pragma unroll
        for (int nt = 0; nt < 8; nt++)
#pragma unroll
            for (int j = 0; j < 4; j++) acc[mt][nt][j] = 0.0f;

    for (int c = 0; c < IN_F / KC; c++) {
        __syncthreads();
        const float* xs = x + (size_t)(row0 + fr) * IN_F + c * KC + fh * 32;
        const float* ws = W + (size_t)fr * IN_F + c * KC + fh * 32;
#pragma unroll
        for (int m = 0; m < 4; m++) {
            float4 va = a_valid ? *(const float4*)(xs + m * 8)
                                : make_float4(0.f, 0.f, 0.f, 0.f);
            float4 vb = a_valid ? *(const float4*)(xs + m * 8 + 4)
                                : make_float4(0.f, 0.f, 0.f, 0.f);
            uint32_t off = frow_base + ((uint32_t)(fh * 64 + m * 16) ^ fxorm);
            float hax = __bfloat162float(__float2bfloat16_rn(va.x));
            float hay = __bfloat162float(__float2bfloat16_rn(va.y));
            float haz = __bfloat162float(__float2bfloat16_rn(va.z));
            float haw = __bfloat162float(__float2bfloat16_rn(va.w));
            float hbx = __bfloat162float(__float2bfloat16_rn(vb.x));
            float hby = __bfloat162float(__float2bfloat16_rn(vb.y));
            float hbz = __bfloat162float(__float2bfloat16_rn(vb.z));
            float hbw = __bfloat162float(__float2bfloat16_rn(vb.w));
            uint4 hi = make_uint4(pk_bf16(hax, hay), pk_bf16(haz, haw),
                                  pk_bf16(hbx, hby), pk_bf16(hbz, hbw));
            uint4 lo = make_uint4(pk_bf16(va.x - hax, va.y - hay),
                                  pk_bf16(va.z - haz, va.w - haw),
                                  pk_bf16(vb.x - hbx, vb.y - hby),
                                  pk_bf16(vb.z - hbz, vb.w - hbw));
            *(uint4*)(smem + OFF_AH + off) = hi;
            *(uint4*)(smem + OFF_AL + off) = lo;

            float4 wa = *(const float4*)(ws + m * 8);
            float4 wb = *(const float4*)(ws + m * 8 + 4);
            float gax = __bfloat162float(__float2bfloat16_rn(wa.x));
            float gay = __bfloat162float(__float2bfloat16_rn(wa.y));
            float gaz = __bfloat162float(__float2bfloat16_rn(wa.z));
            float gaw = __bfloat162float(__float2bfloat16_rn(wa.w));
            float gbx = __bfloat162float(__float2bfloat16_rn(wb.x));
            float gby = __bfloat162float(__float2bfloat16_rn(wb.y));
            float gbz = __bfloat162float(__float2bfloat16_rn(wb.z));
            float gbw = __bfloat162float(__float2bfloat16_rn(wb.w));
            uint4 whi = make_uint4(pk_bf16(gax, gay), pk_bf16(gaz, gaw),
                                   pk_bf16(gbx, gby), pk_bf16(gbz, gbw));
            uint4 wlo = make_uint4(pk_bf16(wa.x - gax, wa.y - gay),
                                   pk_bf16(wa.z - gaz, wa.w - gaw),
                                   pk_bf16(wb.x - gbx, wb.y - gby),
                                   pk_bf16(wb.z - gbz, wb.w - gbw));
            *(uint4*)(smem + OFF_BH + off) = whi;
            *(uint4*)(smem + OFF_BL + off) = wlo;
        }
        __syncthreads();

#pragma unroll
        for (int ks = 0; ks < 4; ks++) {
            uint32_t ah[2][4], al[2][4];
#pragma unroll
            for (int mt = 0; mt < 2; mt++) {
                int row = wm + mt * 16 + (lane & 15);
                uint32_t cb = (uint32_t)(ks * 32 + ((lane >> 4) << 4));
                uint32_t off = row * 128 + (cb ^ ((row & 7) << 4));
                ldsm4(ah[mt], sb + OFF_AH + off);
                ldsm4(al[mt], sb + OFF_AL + off);
            }
#pragma unroll
            for (int ng = 0; ng < 4; ng++) {
                int nrow = wn + ng * 16 + (lane & 7) + ((lane >> 4) << 3);
                uint32_t cb = (uint32_t)(ks * 32 + (((lane >> 3) & 1) << 4));
                uint32_t off = nrow * 128 + (cb ^ ((nrow & 7) << 4));
                uint32_t bh[4], bl[4];
                ldsm4(bh, sb + OFF_BH + off);
                ldsm4(bl, sb + OFF_BL + off);
#pragma unroll
                for (int sub = 0; sub < 2; sub++) {
                    int nt = ng * 2 + sub;
#pragma unroll
                    for (int mt = 0; mt < 2; mt++) {
                        mma16816(acc[mt][nt], ah[mt], bh + sub * 2);
                        mma16816(acc[mt][nt], ah[mt], bl + sub * 2);
                        mma16816(acc[mt][nt], al[mt], bh + sub * 2);
                    }
                }
            }
        }
    }

#pragma unroll
    for (int nt = 0; nt < 8; nt++) {
        int col = wn + nt * 8 + 2 * (lane & 3);
        float2 bb = *(const float2*)(b + col);
#pragma unroll
        for (int mt = 0; mt < 2; mt++) {
            int r0g = row0 + wm + mt * 16 + (lane >> 2);
            if (r0g < n_nodes) {
                float2 v0 = make_float2(acc[mt][nt][0] + bb.x, acc[mt][nt][1] + bb.y);
                *(float2*)(g_support + (size_t)r0g * HID + col) = v0;
            }
            int r1g = r0g + 8;
            if (r1g < n_nodes) {
                float2 v1 = make_float2(acc[mt][nt][2] + bb.x, acc[mt][nt][3] + bb.y);
                *(float2*)(g_support + (size_t)r1g * HID + col) = v1;
            }
        }
    }
}

// ---------------------------------------------------------------------------
// scan_a: per-block reduce of g_cnt (256/block) -> g_bsum
// ---------------------------------------------------------------------------
__global__ __launch_bounds__(SCAN_B) void scan_a_kernel(int n_nodes)
{
    __shared__ int sm[SCAN_B / 32];
    const int t   = threadIdx.x;
    const int idx = blockIdx.x * SCAN_B + t;
    int v = (idx < n_nodes) ? g_cnt[idx] : 0;
#pragma unroll
    for (int o = 16; o > 0; o >>= 1) v += __shfl_down_sync(0xffffffffu, v, o);
    if ((t & 31) == 0) sm[t >> 5] = v;
    __syncthreads();
    if (t < 32) {
        int s = (t < SCAN_B / 32) ? sm[t] : 0;
#pragma unroll
        for (int o = 4; o > 0; o >>= 1) s += __shfl_down_sync(0xffffffffu, s, o);
        if (t == 0) g_bsum[blockIdx.x] = s;
    }
}

// ---------------------------------------------------------------------------
// scan_c: each block (a) scans all g_bsum to get its own exclusive block
// prefix + grand total, (b) block-local exclusive scan of g_cnt, (c) writes
// g_row_start/g_cursor, (d) RE-ZEROES g_cnt (restores the invariant).
// ---------------------------------------------------------------------------
__global__ __launch_bounds__(SCAN_B) void scan_c_kernel(int n_sb, int n_nodes)
{
    __shared__ int bs[SCAN_B];
    __shared__ int sm[SCAN_B];
    const int t   = threadIdx.x;
    const int idx = blockIdx.x * SCAN_B + t;

    // inclusive scan of block sums (196 values)
    int bv = (t < n_sb) ? g_bsum[t] : 0;
    bs[t] = bv;
    __syncthreads();
#pragma unroll
    for (int o = 1; o < SCAN_B; o <<= 1) {
        int u = (t >= o) ? bs[t - o] : 0;
        __syncthreads();
        bs[t] += u;
        __syncthreads();
    }
    const int blk_prefix = (blockIdx.x > 0) ? bs[blockIdx.x - 1] : 0;
    if (blockIdx.x == 0 && t == 0) g_row_start[n_nodes] = bs[n_sb - 1];

    // block-local inclusive scan of counts
    int v = (idx < n_nodes) ? g_cnt[idx] : 0;
    sm[t] = v;
    __syncthreads();
#pragma unroll
    for (int o = 1; o < SCAN_B; o <<= 1) {
        int u = (t >= o) ? sm[t - o] : 0;
        __syncthreads();
        sm[t] += u;
        __syncthreads();
    }
    if (idx < n_nodes) {
        int excl = blk_prefix + sm[t] - v;
        g_row_start[idx] = excl;
        g_cursor[idx]    = excl;
        g_cnt[idx]       = 0;          // restore invariant for next call
    }
}

// ---------------------------------------------------------------------------
// fill: one 8B store + one counter atomic per edge
// ---------------------------------------------------------------------------
__global__ __launch_bounds__(256) void fill_kernel(
    const int*   __restrict__ adj_row,
    const int*   __restrict__ adj_col,
    const float* __restrict__ adj_val,
    int n_edges)
{
    int e = blockIdx.x * blockDim.x + threadIdx.x;
    if (e >= n_edges) return;
    int r   = adj_row[e];
    int pos = atomicAdd(&g_cursor[r], 1);
    g_edge[pos] = make_int2(adj_col[e], __float_as_int(adj_val[e]));
}

// ---------------------------------------------------------------------------
// gather: warp-per-row, unroll-4 for MLP; writes every row (no atomics)
// ---------------------------------------------------------------------------
__global__ __launch_bounds__(256) void row_gather_kernel(
    float* __restrict__ out, int n_nodes)
{
    const int row  = (blockIdx.x * blockDim.x + threadIdx.x) >> 5;
    const int lane = threadIdx.x & 31;
    if (row >= n_nodes) return;

    const int s0 = g_row_start[row];
    const int s1 = g_row_start[row + 1];

    const float4* sup4 = reinterpret_cast<const float4*>(g_support);
    float4 acc = make_float4(0.f, 0.f, 0.f, 0.f);

    int e = s0;
    for (; e + 3 < s1; e += 4) {
        int2 ev0 = g_edge[e];
        int2 ev1 = g_edge[e + 1];
        int2 ev2 = g_edge[e + 2];
        int2 ev3 = g_edge[e + 3];
        float4 a0 = sup4[(size_t)ev0.x * (HID / 4) + lane];
        float4 a1 = sup4[(size_t)ev1.x * (HID / 4) + lane];
        float4 a2 = sup4[(size_t)ev2.x * (HID / 4) + lane];
        float4 a3 = sup4[(size_t)ev3.x * (HID / 4) + lane];
        float v0 = __int_as_float(ev0.y), v1 = __int_as_float(ev1.y);
        float v2 = __int_as_float(ev2.y), v3 = __int_as_float(ev3.y);
        acc.x += v0 * a0.x + v1 * a1.x + v2 * a2.x + v3 * a3.x;
        acc.y += v0 * a0.y + v1 * a1.y + v2 * a2.y + v3 * a3.y;
        acc.z += v0 * a0.z + v1 * a1.z + v2 * a2.z + v3 * a3.z;
        acc.w += v0 * a0.w + v1 * a1.w + v2 * a2.w + v3 * a3.w;
    }
    for (; e < s1; e++) {
        int2 ev = g_edge[e];
        float4 sv = sup4[(size_t)ev.x * (HID / 4) + lane];
        float v = __int_as_float(ev.y);
        acc.x += v * sv.x; acc.y += v * sv.y;
        acc.z += v * sv.z; acc.w += v * sv.w;
    }

    reinterpret_cast<float4*>(out)[(size_t)row * (HID / 4) + lane] = acc;
}

// ---------------------------------------------------------------------------
// Launch: inputs: x, adj_row, adj_col, adj_val, W, b
// ---------------------------------------------------------------------------
extern "C" void kernel_launch(void* const* d_in, const int* in_sizes, int n_in,
                              void* d_out, int out_size)
{
    const float* x       = (const float*)d_in[0];
    const int*   adj_row = (const int*)  d_in[1];
    const int*   adj_col = (const int*)  d_in[2];
    const float* adj_val = (const float*)d_in[3];
    const float* W       = (const float*)d_in[4];
    const float* b       = (const float*)d_in[5];
    float*       out     = (float*)d_out;

    const int n_nodes = in_sizes[0] / IN_F;
    const int n_edges = in_sizes[1];
    const int n_sb    = (n_nodes + SCAN_B - 1) / SCAN_B;
    const int gemm_blocks = (n_nodes + TILE_M - 1) / TILE_M;

    cudaFuncSetAttribute(gemm_hist_kernel,
                         cudaFuncAttributeMaxDynamicSharedMemorySize, GEMM_SMEM);

    // GEMM + histogram in one fat launch (hist hides in the GEMM tail wave)
    gemm_hist_kernel<<<gemm_blocks + HIST_BLOCKS, 256, GEMM_SMEM>>>(
        x, W, b, adj_row, n_nodes, n_edges, gemm_blocks);

    scan_a_kernel<<<n_sb, SCAN_B>>>(n_nodes);
    scan_c_kernel<<<n_sb, SCAN_B>>>(n_sb, n_nodes);
    fill_kernel<<<(n_edges + 255) / 256, 256>>>(adj_row, adj_col, adj_val, n_edges);
    row_gather_kernel<<<(n_nodes * 32 + 255) / 256, 256>>>(out, n_nodes);
}

// round 7
// speedup vs baseline: 3.6553x; 1.1417x over previous
#include <cuda_runtime.h>
#include <cuda_bf16.h>
#include <cstdint>

#define IN_F 256
#define HID  128
#define TILE_M 128
#define KC   64
#define MAX_NODES 50000
#define MAX_EDGES 800000
#define SCAN_B   256

// Scratch (device globals; no device-memory allocation APIs anywhere).
// INVARIANT: g_cnt is all-zero at kernel_launch entry; scan_c re-zeroes it.
__device__ float g_support[MAX_NODES * HID];
__device__ int   g_cnt[MAX_NODES];
__device__ int   g_row_start[MAX_NODES + 1];
__device__ int   g_cursor[MAX_NODES];
__device__ int2  g_edge[MAX_EDGES];
__device__ int   g_bsum[SCAN_B];
// Pre-split W, stored as pre-swizzled smem tile images: 4 chunks x 16KB.
__device__ unsigned char g_Wh[4 * 16384];
__device__ unsigned char g_Wl[4 * 16384];

// ---------------------------------------------------------------------------
// Helpers (plain sm_80-era PTX; nothing arch-'a' gated)
// ---------------------------------------------------------------------------
__device__ __forceinline__ uint32_t smem_to_u32(const void* p) {
    uint32_t a;
    asm("{ .reg .u64 t; cvta.to.shared.u64 t, %1; cvt.u32.u64 %0, t; }"
        : "=r"(a) : "l"(p));
    return a;
}

__device__ __forceinline__ void ldsm4(uint32_t* r, uint32_t addr) {
    asm volatile("ldmatrix.sync.aligned.m8n8.x4.shared.b16 {%0,%1,%2,%3}, [%4];"
        : "=r"(r[0]), "=r"(r[1]), "=r"(r[2]), "=r"(r[3]) : "r"(addr));
}

__device__ __forceinline__ void mma16816(float* c, const uint32_t* a, const uint32_t* b) {
    asm volatile("mma.sync.aligned.m16n8k16.row.col.f32.bf16.bf16.f32 "
        "{%0,%1,%2,%3}, {%4,%5,%6,%7}, {%8,%9}, {%0,%1,%2,%3};"
        : "+f"(c[0]), "+f"(c[1]), "+f"(c[2]), "+f"(c[3])
        : "r"(a[0]), "r"(a[1]), "r"(a[2]), "r"(a[3]), "r"(b[0]), "r"(b[1]));
}

__device__ __forceinline__ uint32_t pk_bf16(float a, float b) {
    __nv_bfloat162 p = __floats2bfloat162_rn(a, b);
    return reinterpret_cast<uint32_t&>(p);
}

// smem tile layout: 128 rows x 64 bf16 = 128B/row; SW128 xor swizzle.
#define OFF_AH 0
#define OFF_AL 16384
#define OFF_BH 32768
#define OFF_BL 49152
#define GEMM_SMEM 65536

// ---------------------------------------------------------------------------
// wsplit: W [128 x 256] fp32 -> hi/lo bf16, stored pre-swizzled per chunk.
// 4096 groups of 8 k-values; one group per thread.
// ---------------------------------------------------------------------------
__global__ __launch_bounds__(256) void wsplit_kernel(const float* __restrict__ W)
{
    int g  = blockIdx.x * blockDim.x + threadIdx.x;   // 0..4095
    int r  = g >> 5;                                  // HID row 0..127
    int kg = g & 31;                                  // 16B group within row
    int c  = kg >> 3;                                 // chunk 0..3
    const float* src = W + r * IN_F + kg * 8;
    float4 va = *(const float4*)(src);
    float4 vb = *(const float4*)(src + 4);
    float hax = __bfloat162float(__float2bfloat16_rn(va.x));
    float hay = __bfloat162float(__float2bfloat16_rn(va.y));
    float haz = __bfloat162float(__float2bfloat16_rn(va.z));
    float haw = __bfloat162float(__float2bfloat16_rn(va.w));
    float hbx = __bfloat162float(__float2bfloat16_rn(vb.x));
    float hby = __bfloat162float(__float2bfloat16_rn(vb.y));
    float hbz = __bfloat162float(__float2bfloat16_rn(vb.z));
    float hbw = __bfloat162float(__float2bfloat16_rn(vb.w));
    uint4 hi = make_uint4(pk_bf16(hax, hay), pk_bf16(haz, haw),
                          pk_bf16(hbx, hby), pk_bf16(hbz, hbw));
    uint4 lo = make_uint4(pk_bf16(va.x - hax, va.y - hay),
                          pk_bf16(va.z - haz, va.w - haw),
                          pk_bf16(vb.x - hbx, vb.y - hby),
                          pk_bf16(vb.z - hbz, vb.w - hbw));
    uint32_t off = (uint32_t)c * 16384 + r * 128 +
                   (((uint32_t)(kg & 7) * 16) ^ ((r & 7) << 4));
    *(uint4*)(g_Wh + off) = hi;
    *(uint4*)(g_Wl + off) = lo;
}

// ---------------------------------------------------------------------------
// GEMM: support = x @ W^T + b, bf16 split 3-pass mma.sync.
// B tiles copied from pre-split g_Wh/g_Wl (no per-CTA conversion).
// ---------------------------------------------------------------------------
__global__ __launch_bounds__(256, 2) void gcn_linear_mma_kernel(
    const float* __restrict__ x,
    const float* __restrict__ b,
    int n_nodes)
{
    extern __shared__ char smem[];
    const uint32_t sb = smem_to_u32(smem);
    const int t    = threadIdx.x;
    const int wid  = t >> 5;
    const int lane = t & 31;
    const int row0 = blockIdx.x * TILE_M;

    const int fr = t & 127;
    const int fh = t >> 7;
    const uint32_t frow_base = fr * 128;
    const uint32_t fxorm = (fr & 7) << 4;
    const bool a_valid = (row0 + fr) < n_nodes;

    const int wm = (wid & 3) * 32;
    const int wn = (wid >> 2) * 64;

    float acc[2][8][4];
#pragma unroll
    for (int mt = 0; mt < 2; mt++)
#pragma unroll
        for (int nt = 0; nt < 8; nt++)
#pragma unroll
            for (int j = 0; j < 4; j++) acc[mt][nt][j] = 0.0f;

    for (int c = 0; c < IN_F / KC; c++) {
        __syncthreads();
        // ---- A fill: split-convert x chunk ----
        const float* xs = x + (size_t)(row0 + fr) * IN_F + c * KC + fh * 32;
#pragma unroll
        for (int m = 0; m < 4; m++) {
            float4 va = a_valid ? *(const float4*)(xs + m * 8)
                                : make_float4(0.f, 0.f, 0.f, 0.f);
            float4 vb = a_valid ? *(const float4*)(xs + m * 8 + 4)
                                : make_float4(0.f, 0.f, 0.f, 0.f);
            uint32_t off = frow_base + ((uint32_t)(fh * 64 + m * 16) ^ fxorm);
            float hax = __bfloat162float(__float2bfloat16_rn(va.x));
            float hay = __bfloat162float(__float2bfloat16_rn(va.y));
            float haz = __bfloat162float(__float2bfloat16_rn(va.z));
            float haw = __bfloat162float(__float2bfloat16_rn(va.w));
            float hbx = __bfloat162float(__float2bfloat16_rn(vb.x));
            float hby = __bfloat162float(__float2bfloat16_rn(vb.y));
            float hbz = __bfloat162float(__float2bfloat16_rn(vb.z));
            float hbw = __bfloat162float(__float2bfloat16_rn(vb.w));
            uint4 hi = make_uint4(pk_bf16(hax, hay), pk_bf16(haz, haw),
                                  pk_bf16(hbx, hby), pk_bf16(hbz, hbw));
            uint4 lo = make_uint4(pk_bf16(va.x - hax, va.y - hay),
                                  pk_bf16(va.z - haz, va.w - haw),
                                  pk_bf16(vb.x - hbx, vb.y - hby),
                                  pk_bf16(vb.z - hbz, vb.w - hbw));
            *(uint4*)(smem + OFF_AH + off) = hi;
            *(uint4*)(smem + OFF_AL + off) = lo;
        }
        // ---- B fill: straight copy of pre-swizzled W images ----
        {
            const uint4* srcH = (const uint4*)(g_Wh + (size_t)c * 16384);
            const uint4* srcL = (const uint4*)(g_Wl + (size_t)c * 16384);
            uint4* dstH = (uint4*)(smem + OFF_BH);
            uint4* dstL = (uint4*)(smem + OFF_BL);
#pragma unroll
            for (int i = 0; i < 4; i++) {
                int idx = t + i * 256;
                dstH[idx] = srcH[idx];
                dstL[idx] = srcL[idx];
            }
        }
        __syncthreads();

#pragma unroll
        for (int ks = 0; ks < 4; ks++) {
            uint32_t ah[2][4], al[2][4];
#pragma unroll
            for (int mt = 0; mt < 2; mt++) {
                int row = wm + mt * 16 + (lane & 15);
                uint32_t cb = (uint32_t)(ks * 32 + ((lane >> 4) << 4));
                uint32_t off = row * 128 + (cb ^ ((row & 7) << 4));
                ldsm4(ah[mt], sb + OFF_AH + off);
                ldsm4(al[mt], sb + OFF_AL + off);
            }
#pragma unroll
            for (int ng = 0; ng < 4; ng++) {
                int nrow = wn + ng * 16 + (lane & 7) + ((lane >> 4) << 3);
                uint32_t cb = (uint32_t)(ks * 32 + (((lane >> 3) & 1) << 4));
                uint32_t off = nrow * 128 + (cb ^ ((nrow & 7) << 4));
                uint32_t bh[4], bl[4];
                ldsm4(bh, sb + OFF_BH + off);
                ldsm4(bl, sb + OFF_BL + off);
#pragma unroll
                for (int sub = 0; sub < 2; sub++) {
                    int nt = ng * 2 + sub;
#pragma unroll
                    for (int mt = 0; mt < 2; mt++) {
                        mma16816(acc[mt][nt], ah[mt], bh + sub * 2);
                        mma16816(acc[mt][nt], ah[mt], bl + sub * 2);
                        mma16816(acc[mt][nt], al[mt], bh + sub * 2);
                    }
                }
            }
        }
    }

#pragma unroll
    for (int nt = 0; nt < 8; nt++) {
        int col = wn + nt * 8 + 2 * (lane & 3);
        float2 bb = *(const float2*)(b + col);
#pragma unroll
        for (int mt = 0; mt < 2; mt++) {
            int r0g = row0 + wm + mt * 16 + (lane >> 2);
            if (r0g < n_nodes) {
                float2 v0 = make_float2(acc[mt][nt][0] + bb.x, acc[mt][nt][1] + bb.y);
                *(float2*)(g_support + (size_t)r0g * HID + col) = v0;
            }
            int r1g = r0g + 8;
            if (r1g < n_nodes) {
                float2 v1 = make_float2(acc[mt][nt][2] + bb.x, acc[mt][nt][3] + bb.y);
                *(float2*)(g_support + (size_t)r1g * HID + col) = v1;
            }
        }
    }
}

// ---------------------------------------------------------------------------
// hist: edge histogram into g_cnt (relies on zero-invariant)
// ---------------------------------------------------------------------------
__global__ __launch_bounds__(256) void hist_kernel(
    const int* __restrict__ adj_row, int n_edges)
{
    int e = blockIdx.x * blockDim.x + threadIdx.x;
    if (e < n_edges) atomicAdd(&g_cnt[adj_row[e]], 1);
}

// scan_a: per-block reduce of g_cnt (256/block) -> g_bsum
__global__ __launch_bounds__(SCAN_B) void scan_a_kernel(int n_nodes)
{
    __shared__ int sm[SCAN_B / 32];
    const int t   = threadIdx.x;
    const int idx = blockIdx.x * SCAN_B + t;
    int v = (idx < n_nodes) ? g_cnt[idx] : 0;
#pragma unroll
    for (int o = 16; o > 0; o >>= 1) v += __shfl_down_sync(0xffffffffu, v, o);
    if ((t & 31) == 0) sm[t >> 5] = v;
    __syncthreads();
    if (t < 32) {
        int s = (t < SCAN_B / 32) ? sm[t] : 0;
#pragma unroll
        for (int o = 4; o > 0; o >>= 1) s += __shfl_down_sync(0xffffffffu, s, o);
        if (t == 0) g_bsum[blockIdx.x] = s;
    }
}

// scan_c: block prefix from g_bsum + local scan; writes row_start/cursor;
// re-zeroes g_cnt (restores invariant).
__global__ __launch_bounds__(SCAN_B) void scan_c_kernel(int n_sb, int n_nodes)
{
    __shared__ int bs[SCAN_B];
    __shared__ int sm[SCAN_B];
    const int t   = threadIdx.x;
    const int idx = blockIdx.x * SCAN_B + t;

    int bv = (t < n_sb) ? g_bsum[t] : 0;
    bs[t] = bv;
    __syncthreads();
#pragma unroll
    for (int o = 1; o < SCAN_B; o <<= 1) {
        int u = (t >= o) ? bs[t - o] : 0;
        __syncthreads();
        bs[t] += u;
        __syncthreads();
    }
    const int blk_prefix = (blockIdx.x > 0) ? bs[blockIdx.x - 1] : 0;
    if (blockIdx.x == 0 && t == 0) g_row_start[n_nodes] = bs[n_sb - 1];

    int v = (idx < n_nodes) ? g_cnt[idx] : 0;
    sm[t] = v;
    __syncthreads();
#pragma unroll
    for (int o = 1; o < SCAN_B; o <<= 1) {
        int u = (t >= o) ? sm[t - o] : 0;
        __syncthreads();
        sm[t] += u;
        __syncthreads();
    }
    if (idx < n_nodes) {
        int excl = blk_prefix + sm[t] - v;
        g_row_start[idx] = excl;
        g_cursor[idx]    = excl;
        g_cnt[idx]       = 0;
    }
}

// fill: 4 independent edges per thread (hide ATOMG return latency)
__global__ __launch_bounds__(256) void fill_kernel(
    const int*   __restrict__ adj_row,
    const int*   __restrict__ adj_col,
    const float* __restrict__ adj_val,
    int n_edges)
{
    int base = blockIdx.x * 1024 + threadIdx.x;
#pragma unroll
    for (int j = 0; j < 4; j++) {
        int e = base + j * 256;
        if (e < n_edges) {
            int r   = adj_row[e];
            int pos = atomicAdd(&g_cursor[r], 1);
            g_edge[pos] = make_int2(adj_col[e], __float_as_int(adj_val[e]));
        }
    }
}

// gather: warp-per-row, unroll-4; writes every row (no atomics, no memset)
__global__ __launch_bounds__(256) void row_gather_kernel(
    float* __restrict__ out, int n_nodes)
{
    const int row  = (blockIdx.x * blockDim.x + threadIdx.x) >> 5;
    const int lane = threadIdx.x & 31;
    if (row >= n_nodes) return;

    const int s0 = g_row_start[row];
    const int s1 = g_row_start[row + 1];

    const float4* sup4 = reinterpret_cast<const float4*>(g_support);
    float4 acc = make_float4(0.f, 0.f, 0.f, 0.f);

    int e = s0;
    for (; e + 3 < s1; e += 4) {
        int2 ev0 = g_edge[e];
        int2 ev1 = g_edge[e + 1];
        int2 ev2 = g_edge[e + 2];
        int2 ev3 = g_edge[e + 3];
        float4 a0 = sup4[(size_t)ev0.x * (HID / 4) + lane];
        float4 a1 = sup4[(size_t)ev1.x * (HID / 4) + lane];
        float4 a2 = sup4[(size_t)ev2.x * (HID / 4) + lane];
        float4 a3 = sup4[(size_t)ev3.x * (HID / 4) + lane];
        float v0 = __int_as_float(ev0.y), v1 = __int_as_float(ev1.y);
        float v2 = __int_as_float(ev2.y), v3 = __int_as_float(ev3.y);
        acc.x += v0 * a0.x + v1 * a1.x + v2 * a2.x + v3 * a3.x;
        acc.y += v0 * a0.y + v1 * a1.y + v2 * a2.y + v3 * a3.y;
        acc.z += v0 * a0.z + v1 * a1.z + v2 * a2.z + v3 * a3.z;
        acc.w += v0 * a0.w + v1 * a1.w + v2 * a2.w + v3 * a3.w;
    }
    for (; e < s1; e++) {
        int2 ev = g_edge[e];
        float4 sv = sup4[(size_t)ev.x * (HID / 4) + lane];
        float v = __int_as_float(ev.y);
        acc.x += v * sv.x; acc.y += v * sv.y;
        acc.z += v * sv.z; acc.w += v * sv.w;
    }

    reinterpret_cast<float4*>(out)[(size_t)row * (HID / 4) + lane] = acc;
}

// ---------------------------------------------------------------------------
// Side stream + events, created ONCE in a static initializer (no device-mem
// allocation APIs used; falls back to serial on any failure).
// ---------------------------------------------------------------------------
struct AuxStreams {
    cudaStream_t s  = nullptr;
    cudaEvent_t  e1 = nullptr, e2 = nullptr;
    bool ok = false;
    AuxStreams() {
        if (cudaStreamCreateWithFlags(&s, cudaStreamNonBlocking) != cudaSuccess) { s = nullptr; return; }
        if (cudaEventCreateWithFlags(&e1, cudaEventDisableTiming) != cudaSuccess) { e1 = nullptr; return; }
        if (cudaEventCreateWithFlags(&e2, cudaEventDisableTiming) != cudaSuccess) { e2 = nullptr; return; }
        ok = true;
    }
};
static AuxStreams g_aux;

// ---------------------------------------------------------------------------
// Launch: inputs: x, adj_row, adj_col, adj_val, W, b
// Graph shape:  main: wsplit -> gemm ----------------.-> gather
//               side: hist -> scan_a -> scan_c -> fill'
// ---------------------------------------------------------------------------
extern "C" void kernel_launch(void* const* d_in, const int* in_sizes, int n_in,
                              void* d_out, int out_size)
{
    const float* x       = (const float*)d_in[0];
    const int*   adj_row = (const int*)  d_in[1];
    const int*   adj_col = (const int*)  d_in[2];
    const float* adj_val = (const float*)d_in[3];
    const float* W       = (const float*)d_in[4];
    const float* b       = (const float*)d_in[5];
    float*       out     = (float*)d_out;

    const int n_nodes = in_sizes[0] / IN_F;
    const int n_edges = in_sizes[1];
    const int n_sb    = (n_nodes + SCAN_B - 1) / SCAN_B;
    const int gemm_blocks = (n_nodes + TILE_M - 1) / TILE_M;

    cudaFuncSetAttribute(gcn_linear_mma_kernel,
                         cudaFuncAttributeMaxDynamicSharedMemorySize, GEMM_SMEM);

    const bool par = g_aux.ok;
    cudaStream_t sbin = par ? g_aux.s : (cudaStream_t)0;

    if (par) {
        cudaEventRecord(g_aux.e1, 0);
        cudaStreamWaitEvent(sbin, g_aux.e1, 0);
    }

    // Main branch: W pre-split, then tensor GEMM.
    wsplit_kernel<<<16, 256>>>(W);
    gcn_linear_mma_kernel<<<gemm_blocks, 256, GEMM_SMEM>>>(x, b, n_nodes);

    // Binning branch (parallel when par; serial after GEMM otherwise).
    hist_kernel<<<(n_edges + 255) / 256, 256, 0, sbin>>>(adj_row, n_edges);
    scan_a_kernel<<<n_sb, SCAN_B, 0, sbin>>>(n_nodes);
    scan_c_kernel<<<n_sb, SCAN_B, 0, sbin>>>(n_sb, n_nodes);
    fill_kernel<<<(n_edges + 1023) / 1024, 256, 0, sbin>>>(adj_row, adj_col, adj_val, n_edges);

    if (par) {
        cudaEventRecord(g_aux.e2, sbin);
        cudaStreamWaitEvent(0, g_aux.e2, 0);
    }

    // Gather needs both branches complete.
    row_gather_kernel<<<(n_nodes * 32 + 255) / 256, 256>>>(out, n_nodes);
}

// round 8
// speedup vs baseline: 4.0084x; 1.0966x over previous
#include <cuda_runtime.h>
#include <cuda_bf16.h>
#include <cuda_fp16.h>
#include <cstdint>

#define IN_F 256
#define HID  128
#define TILE_M 128
#define KC   64
#define MAX_NODES 50000
#define MAX_EDGES 800000
#define SCAN_B   256

// Scratch (device globals; no device-memory allocation APIs anywhere).
// INVARIANT: g_cnt is all-zero at kernel_launch entry; scan_c re-zeroes it.
__device__ __half g_support_h[MAX_NODES * HID];   // fp16 support (halves gather bytes)
__device__ int    g_cnt[MAX_NODES];
__device__ int    g_row_start[MAX_NODES + 1];
__device__ int    g_cursor[MAX_NODES];
__device__ int2   g_edge[MAX_EDGES];
__device__ int    g_bsum[SCAN_B];
// Pre-split W, stored as pre-swizzled smem tile images: 4 chunks x 16KB.
__device__ unsigned char g_Wh[4 * 16384];
__device__ unsigned char g_Wl[4 * 16384];

// ---------------------------------------------------------------------------
// Helpers (plain sm_80-era PTX; nothing arch-'a' gated)
// ---------------------------------------------------------------------------
__device__ __forceinline__ uint32_t smem_to_u32(const void* p) {
    uint32_t a;
    asm("{ .reg .u64 t; cvta.to.shared.u64 t, %1; cvt.u32.u64 %0, t; }"
        : "=r"(a) : "l"(p));
    return a;
}

__device__ __forceinline__ void ldsm4(uint32_t* r, uint32_t addr) {
    asm volatile("ldmatrix.sync.aligned.m8n8.x4.shared.b16 {%0,%1,%2,%3}, [%4];"
        : "=r"(r[0]), "=r"(r[1]), "=r"(r[2]), "=r"(r[3]) : "r"(addr));
}

__device__ __forceinline__ void mma16816(float* c, const uint32_t* a, const uint32_t* b) {
    asm volatile("mma.sync.aligned.m16n8k16.row.col.f32.bf16.bf16.f32 "
        "{%0,%1,%2,%3}, {%4,%5,%6,%7}, {%8,%9}, {%0,%1,%2,%3};"
        : "+f"(c[0]), "+f"(c[1]), "+f"(c[2]), "+f"(c[3])
        : "r"(a[0]), "r"(a[1]), "r"(a[2]), "r"(a[3]), "r"(b[0]), "r"(b[1]));
}

__device__ __forceinline__ uint32_t pk_bf16(float a, float b) {
    __nv_bfloat162 p = __floats2bfloat162_rn(a, b);
    return reinterpret_cast<uint32_t&>(p);
}

// smem tile layout: 128 rows x 64 bf16 = 128B/row; SW128 xor swizzle.
#define OFF_AH 0
#define OFF_AL 16384
#define OFF_BH 32768
#define OFF_BL 49152
#define GEMM_SMEM 65536

// ---------------------------------------------------------------------------
// wsplit: W [128 x 256] fp32 -> hi/lo bf16, stored pre-swizzled per chunk.
// ---------------------------------------------------------------------------
__global__ __launch_bounds__(256) void wsplit_kernel(const float* __restrict__ W)
{
    int g  = blockIdx.x * blockDim.x + threadIdx.x;   // 0..4095
    int r  = g >> 5;
    int kg = g & 31;
    int c  = kg >> 3;
    const float* src = W + r * IN_F + kg * 8;
    float4 va = *(const float4*)(src);
    float4 vb = *(const float4*)(src + 4);
    float hax = __bfloat162float(__float2bfloat16_rn(va.x));
    float hay = __bfloat162float(__float2bfloat16_rn(va.y));
    float haz = __bfloat162float(__float2bfloat16_rn(va.z));
    float haw = __bfloat162float(__float2bfloat16_rn(va.w));
    float hbx = __bfloat162float(__float2bfloat16_rn(vb.x));
    float hby = __bfloat162float(__float2bfloat16_rn(vb.y));
    float hbz = __bfloat162float(__float2bfloat16_rn(vb.z));
    float hbw = __bfloat162float(__float2bfloat16_rn(vb.w));
    uint4 hi = make_uint4(pk_bf16(hax, hay), pk_bf16(haz, haw),
                          pk_bf16(hbx, hby), pk_bf16(hbz, hbw));
    uint4 lo = make_uint4(pk_bf16(va.x - hax, va.y - hay),
                          pk_bf16(va.z - haz, va.w - haw),
                          pk_bf16(vb.x - hbx, vb.y - hby),
                          pk_bf16(vb.z - hbz, vb.w - hbw));
    uint32_t off = (uint32_t)c * 16384 + r * 128 +
                   (((uint32_t)(kg & 7) * 16) ^ ((r & 7) << 4));
    *(uint4*)(g_Wh + off) = hi;
    *(uint4*)(g_Wl + off) = lo;
}

// ---------------------------------------------------------------------------
// GEMM: support = x @ W^T + b, bf16 split 3-pass mma.sync. fp16 epilogue.
// ---------------------------------------------------------------------------
__global__ __launch_bounds__(256, 2) void gcn_linear_mma_kernel(
    const float* __restrict__ x,
    const float* __restrict__ b,
    int n_nodes)
{
    extern __shared__ char smem[];
    const uint32_t sb = smem_to_u32(smem);
    const int t    = threadIdx.x;
    const int wid  = t >> 5;
    const int lane = t & 31;
    const int row0 = blockIdx.x * TILE_M;

    const int fr = t & 127;
    const int fh = t >> 7;
    const uint32_t frow_base = fr * 128;
    const uint32_t fxorm = (fr & 7) << 4;
    const bool a_valid = (row0 + fr) < n_nodes;

    const int wm = (wid & 3) * 32;
    const int wn = (wid >> 2) * 64;

    float acc[2][8][4];
#pragma unroll
    for (int mt = 0; mt < 2; mt++)
#pragma unroll
        for (int nt = 0; nt < 8; nt++)
#pragma unroll
            for (int j = 0; j < 4; j++) acc[mt][nt][j] = 0.0f;

    for (int c = 0; c < IN_F / KC; c++) {
        __syncthreads();
        // ---- A fill: split-convert x chunk ----
        const float* xs = x + (size_t)(row0 + fr) * IN_F + c * KC + fh * 32;
#pragma unroll
        for (int m = 0; m < 4; m++) {
            float4 va = a_valid ? *(const float4*)(xs + m * 8)
                                : make_float4(0.f, 0.f, 0.f, 0.f);
            float4 vb = a_valid ? *(const float4*)(xs + m * 8 + 4)
                                : make_float4(0.f, 0.f, 0.f, 0.f);
            uint32_t off = frow_base + ((uint32_t)(fh * 64 + m * 16) ^ fxorm);
            float hax = __bfloat162float(__float2bfloat16_rn(va.x));
            float hay = __bfloat162float(__float2bfloat16_rn(va.y));
            float haz = __bfloat162float(__float2bfloat16_rn(va.z));
            float haw = __bfloat162float(__float2bfloat16_rn(va.w));
            float hbx = __bfloat162float(__float2bfloat16_rn(vb.x));
            float hby = __bfloat162float(__float2bfloat16_rn(vb.y));
            float hbz = __bfloat162float(__float2bfloat16_rn(vb.z));
            float hbw = __bfloat162float(__float2bfloat16_rn(vb.w));
            uint4 hi = make_uint4(pk_bf16(hax, hay), pk_bf16(haz, haw),
                                  pk_bf16(hbx, hby), pk_bf16(hbz, hbw));
            uint4 lo = make_uint4(pk_bf16(va.x - hax, va.y - hay),
                                  pk_bf16(va.z - haz, va.w - haw),
                                  pk_bf16(vb.x - hbx, vb.y - hby),
                                  pk_bf16(vb.z - hbz, vb.w - hbw));
            *(uint4*)(smem + OFF_AH + off) = hi;
            *(uint4*)(smem + OFF_AL + off) = lo;
        }
        // ---- B fill: straight copy of pre-swizzled W images ----
        {
            const uint4* srcH = (const uint4*)(g_Wh + (size_t)c * 16384);
            const uint4* srcL = (const uint4*)(g_Wl + (size_t)c * 16384);
            uint4* dstH = (uint4*)(smem + OFF_BH);
            uint4* dstL = (uint4*)(smem + OFF_BL);
#pragma unroll
            for (int i = 0; i < 4; i++) {
                int idx = t + i * 256;
                dstH[idx] = srcH[idx];
                dstL[idx] = srcL[idx];
            }
        }
        __syncthreads();

#pragma unroll
        for (int ks = 0; ks < 4; ks++) {
            uint32_t ah[2][4], al[2][4];
#pragma unroll
            for (int mt = 0; mt < 2; mt++) {
                int row = wm + mt * 16 + (lane & 15);
                uint32_t cb = (uint32_t)(ks * 32 + ((lane >> 4) << 4));
                uint32_t off = row * 128 + (cb ^ ((row & 7) << 4));
                ldsm4(ah[mt], sb + OFF_AH + off);
                ldsm4(al[mt], sb + OFF_AL + off);
            }
#pragma unroll
            for (int ng = 0; ng < 4; ng++) {
                int nrow = wn + ng * 16 + (lane & 7) + ((lane >> 4) << 3);
                uint32_t cb = (uint32_t)(ks * 32 + (((lane >> 3) & 1) << 4));
                uint32_t off = nrow * 128 + (cb ^ ((nrow & 7) << 4));
                uint32_t bh[4], bl[4];
                ldsm4(bh, sb + OFF_BH + off);
                ldsm4(bl, sb + OFF_BL + off);
#pragma unroll
                for (int sub = 0; sub < 2; sub++) {
                    int nt = ng * 2 + sub;
#pragma unroll
                    for (int mt = 0; mt < 2; mt++) {
                        mma16816(acc[mt][nt], ah[mt], bh + sub * 2);
                        mma16816(acc[mt][nt], ah[mt], bl + sub * 2);
                        mma16816(acc[mt][nt], al[mt], bh + sub * 2);
                    }
                }
            }
        }
    }

    // ---- epilogue: bias + fp16 store (half2 per fragment pair) ----
#pragma unroll
    for (int nt = 0; nt < 8; nt++) {
        int col = wn + nt * 8 + 2 * (lane & 3);
        float2 bb = *(const float2*)(b + col);
#pragma unroll
        for (int mt = 0; mt < 2; mt++) {
            int r0g = row0 + wm + mt * 16 + (lane >> 2);
            if (r0g < n_nodes) {
                __half2 h0 = __floats2half2_rn(acc[mt][nt][0] + bb.x,
                                               acc[mt][nt][1] + bb.y);
                *(__half2*)(g_support_h + (size_t)r0g * HID + col) = h0;
            }
            int r1g = r0g + 8;
            if (r1g < n_nodes) {
                __half2 h1 = __floats2half2_rn(acc[mt][nt][2] + bb.x,
                                               acc[mt][nt][3] + bb.y);
                *(__half2*)(g_support_h + (size_t)r1g * HID + col) = h1;
            }
        }
    }
}

// ---------------------------------------------------------------------------
// hist: edge histogram into g_cnt (relies on zero-invariant)
// ---------------------------------------------------------------------------
__global__ __launch_bounds__(256) void hist_kernel(
    const int* __restrict__ adj_row, int n_edges)
{
    int e = blockIdx.x * blockDim.x + threadIdx.x;
    if (e < n_edges) atomicAdd(&g_cnt[adj_row[e]], 1);
}

// scan_a: per-block reduce of g_cnt (256/block) -> g_bsum
__global__ __launch_bounds__(SCAN_B) void scan_a_kernel(int n_nodes)
{
    __shared__ int sm[SCAN_B / 32];
    const int t   = threadIdx.x;
    const int idx = blockIdx.x * SCAN_B + t;
    int v = (idx < n_nodes) ? g_cnt[idx] : 0;
#pragma unroll
    for (int o = 16; o > 0; o >>= 1) v += __shfl_down_sync(0xffffffffu, v, o);
    if ((t & 31) == 0) sm[t >> 5] = v;
    __syncthreads();
    if (t < 32) {
        int s = (t < SCAN_B / 32) ? sm[t] : 0;
#pragma unroll
        for (int o = 4; o > 0; o >>= 1) s += __shfl_down_sync(0xffffffffu, s, o);
        if (t == 0) g_bsum[blockIdx.x] = s;
    }
}

// scan_c: block prefix from g_bsum + local scan; writes row_start/cursor;
// re-zeroes g_cnt (restores invariant).
__global__ __launch_bounds__(SCAN_B) void scan_c_kernel(int n_sb, int n_nodes)
{
    __shared__ int bs[SCAN_B];
    __shared__ int sm[SCAN_B];
    const int t   = threadIdx.x;
    const int idx = blockIdx.x * SCAN_B + t;

    int bv = (t < n_sb) ? g_bsum[t] : 0;
    bs[t] = bv;
    __syncthreads();
#pragma unroll
    for (int o = 1; o < SCAN_B; o <<= 1) {
        int u = (t >= o) ? bs[t - o] : 0;
        __syncthreads();
        bs[t] += u;
        __syncthreads();
    }
    const int blk_prefix = (blockIdx.x > 0) ? bs[blockIdx.x - 1] : 0;
    if (blockIdx.x == 0 && t == 0) g_row_start[n_nodes] = bs[n_sb - 1];

    int v = (idx < n_nodes) ? g_cnt[idx] : 0;
    sm[t] = v;
    __syncthreads();
#pragma unroll
    for (int o = 1; o < SCAN_B; o <<= 1) {
        int u = (t >= o) ? sm[t - o] : 0;
        __syncthreads();
        sm[t] += u;
        __syncthreads();
    }
    if (idx < n_nodes) {
        int excl = blk_prefix + sm[t] - v;
        g_row_start[idx] = excl;
        g_cursor[idx]    = excl;
        g_cnt[idx]       = 0;
    }
}

// fill: 4 independent edges per thread (hide ATOMG return latency)
__global__ __launch_bounds__(256) void fill_kernel(
    const int*   __restrict__ adj_row,
    const int*   __restrict__ adj_col,
    const float* __restrict__ adj_val,
    int n_edges)
{
    int base = blockIdx.x * 1024 + threadIdx.x;
#pragma unroll
    for (int j = 0; j < 4; j++) {
        int e = base + j * 256;
        if (e < n_edges) {
            int r   = adj_row[e];
            int pos = atomicAdd(&g_cursor[r], 1);
            g_edge[pos] = make_int2(adj_col[e], __float_as_int(adj_val[e]));
        }
    }
}

// ---------------------------------------------------------------------------
// gather: warp-per-row, fp16 support (uint2 = 4 halves per lane), fp32 accum.
// Writes every row (no atomics, no memset).
// ---------------------------------------------------------------------------
__global__ __launch_bounds__(256) void row_gather_kernel(
    float* __restrict__ out, int n_nodes)
{
    const int row  = (blockIdx.x * blockDim.x + threadIdx.x) >> 5;
    const int lane = threadIdx.x & 31;
    if (row >= n_nodes) return;

    const int s0 = g_row_start[row];
    const int s1 = g_row_start[row + 1];

    const uint2* sup = reinterpret_cast<const uint2*>(g_support_h);
    float4 acc = make_float4(0.f, 0.f, 0.f, 0.f);

    int e = s0;
    for (; e + 3 < s1; e += 4) {
        int2 ev0 = g_edge[e];
        int2 ev1 = g_edge[e + 1];
        int2 ev2 = g_edge[e + 2];
        int2 ev3 = g_edge[e + 3];
        uint2 r0 = sup[(size_t)ev0.x * 32 + lane];
        uint2 r1 = sup[(size_t)ev1.x * 32 + lane];
        uint2 r2 = sup[(size_t)ev2.x * 32 + lane];
        uint2 r3 = sup[(size_t)ev3.x * 32 + lane];
        float v0 = __int_as_float(ev0.y), v1 = __int_as_float(ev1.y);
        float v2 = __int_as_float(ev2.y), v3 = __int_as_float(ev3.y);
        float2 a01 = __half22float2(*(const __half2*)&r0.x);
        float2 a23 = __half22float2(*(const __half2*)&r0.y);
        float2 b01 = __half22float2(*(const __half2*)&r1.x);
        float2 b23 = __half22float2(*(const __half2*)&r1.y);
        float2 c01 = __half22float2(*(const __half2*)&r2.x);
        float2 c23 = __half22float2(*(const __half2*)&r2.y);
        float2 d01 = __half22float2(*(const __half2*)&r3.x);
        float2 d23 = __half22float2(*(const __half2*)&r3.y);
        acc.x += v0 * a01.x + v1 * b01.x + v2 * c01.x + v3 * d01.x;
        acc.y += v0 * a01.y + v1 * b01.y + v2 * c01.y + v3 * d01.y;
        acc.z += v0 * a23.x + v1 * b23.x + v2 * c23.x + v3 * d23.x;
        acc.w += v0 * a23.y + v1 * b23.y + v2 * c23.y + v3 * d23.y;
    }
    for (; e < s1; e++) {
        int2 ev = g_edge[e];
        uint2 r0 = sup[(size_t)ev.x * 32 + lane];
        float v = __int_as_float(ev.y);
        float2 a01 = __half22float2(*(const __half2*)&r0.x);
        float2 a23 = __half22float2(*(const __half2*)&r0.y);
        acc.x += v * a01.x; acc.y += v * a01.y;
        acc.z += v * a23.x; acc.w += v * a23.y;
    }

    reinterpret_cast<float4*>(out)[(size_t)row * 32 + lane] = acc;
}

// ---------------------------------------------------------------------------
// Side stream + events, created ONCE (no device-mem allocation APIs).
// ---------------------------------------------------------------------------
struct AuxStreams {
    cudaStream_t s  = nullptr;
    cudaEvent_t  e1 = nullptr, e2 = nullptr;
    bool ok = false;
    AuxStreams() {
        if (cudaStreamCreateWithFlags(&s, cudaStreamNonBlocking) != cudaSuccess) { s = nullptr; return; }
        if (cudaEventCreateWithFlags(&e1, cudaEventDisableTiming) != cudaSuccess) { e1 = nullptr; return; }
        if (cudaEventCreateWithFlags(&e2, cudaEventDisableTiming) != cudaSuccess) { e2 = nullptr; return; }
        ok = true;
    }
};
static AuxStreams g_aux;

// ---------------------------------------------------------------------------
// Launch: inputs: x, adj_row, adj_col, adj_val, W, b
// Graph:  main: wsplit -> gemm ----------------.-> gather
//         side: hist -> scan_a -> scan_c -> fill'
// ---------------------------------------------------------------------------
extern "C" void kernel_launch(void* const* d_in, const int* in_sizes, int n_in,
                              void* d_out, int out_size)
{
    const float* x       = (const float*)d_in[0];
    const int*   adj_row = (const int*)  d_in[1];
    const int*   adj_col = (const int*)  d_in[2];
    const float* adj_val = (const float*)d_in[3];
    const float* W       = (const float*)d_in[4];
    const float* b       = (const float*)d_in[5];
    float*       out     = (float*)d_out;

    const int n_nodes = in_sizes[0] / IN_F;
    const int n_edges = in_sizes[1];
    const int n_sb    = (n_nodes + SCAN_B - 1) / SCAN_B;
    const int gemm_blocks = (n_nodes + TILE_M - 1) / TILE_M;

    cudaFuncSetAttribute(gcn_linear_mma_kernel,
                         cudaFuncAttributeMaxDynamicSharedMemorySize, GEMM_SMEM);

    const bool par = g_aux.ok;
    cudaStream_t sbin = par ? g_aux.s : (cudaStream_t)0;

    if (par) {
        cudaEventRecord(g_aux.e1, 0);
        cudaStreamWaitEvent(sbin, g_aux.e1, 0);
    }

    wsplit_kernel<<<16, 256>>>(W);
    gcn_linear_mma_kernel<<<gemm_blocks, 256, GEMM_SMEM>>>(x, b, n_nodes);

    hist_kernel<<<(n_edges + 255) / 256, 256, 0, sbin>>>(adj_row, n_edges);
    scan_a_kernel<<<n_sb, SCAN_B, 0, sbin>>>(n_nodes);
    scan_c_kernel<<<n_sb, SCAN_B, 0, sbin>>>(n_sb, n_nodes);
    fill_kernel<<<(n_edges + 1023) / 1024, 256, 0, sbin>>>(adj_row, adj_col, adj_val, n_edges);

    if (par) {
        cudaEventRecord(g_aux.e2, sbin);
        cudaStreamWaitEvent(0, g_aux.e2, 0);
    }

    row_gather_kernel<<<(n_nodes * 32 + 255) / 256, 256>>>(out, n_nodes);
}

// round 9
// speedup vs baseline: 4.0439x; 1.0089x over previous
#include <cuda_runtime.h>
#include <cuda_bf16.h>
#include <cuda_fp16.h>
#include <cstdint>

#define IN_F 256
#define HID  128
#define TILE_M 128
#define KC   64
#define MAX_NODES 50000
#define MAX_EDGES 800000
#define SCAN_B   256

// Scratch (device globals; no device-memory allocation APIs anywhere).
// INVARIANT: g_cnt is all-zero at kernel_launch entry; scan_c re-zeroes it.
__device__ __half g_support_h[MAX_NODES * HID];   // fp16 support
__device__ int    g_cnt[MAX_NODES];
__device__ int    g_row_start[MAX_NODES + 1];
__device__ int    g_cursor[MAX_NODES];
__device__ int2   g_edge[MAX_EDGES];
__device__ int    g_bsum[SCAN_B];
// Pre-split W, stored as pre-swizzled smem tile images: 4 chunks x 16KB.
__device__ unsigned char g_Wh[4 * 16384];
__device__ unsigned char g_Wl[4 * 16384];

// ---------------------------------------------------------------------------
// Helpers (plain sm_80-era PTX; nothing arch-'a' gated)
// ---------------------------------------------------------------------------
__device__ __forceinline__ uint32_t smem_to_u32(const void* p) {
    uint32_t a;
    asm("{ .reg .u64 t; cvta.to.shared.u64 t, %1; cvt.u32.u64 %0, t; }"
        : "=r"(a) : "l"(p));
    return a;
}

__device__ __forceinline__ void ldsm4(uint32_t* r, uint32_t addr) {
    asm volatile("ldmatrix.sync.aligned.m8n8.x4.shared.b16 {%0,%1,%2,%3}, [%4];"
        : "=r"(r[0]), "=r"(r[1]), "=r"(r[2]), "=r"(r[3]) : "r"(addr));
}

__device__ __forceinline__ void mma16816(float* c, const uint32_t* a, const uint32_t* b) {
    asm volatile("mma.sync.aligned.m16n8k16.row.col.f32.bf16.bf16.f32 "
        "{%0,%1,%2,%3}, {%4,%5,%6,%7}, {%8,%9}, {%0,%1,%2,%3};"
        : "+f"(c[0]), "+f"(c[1]), "+f"(c[2]), "+f"(c[3])
        : "r"(a[0]), "r"(a[1]), "r"(a[2]), "r"(a[3]), "r"(b[0]), "r"(b[1]));
}

__device__ __forceinline__ uint32_t pk_bf16(float a, float b) {
    __nv_bfloat162 p = __floats2bfloat162_rn(a, b);
    return reinterpret_cast<uint32_t&>(p);
}

#define CP_ASYNC16(dst, src) \
    asm volatile("cp.async.cg.shared.global [%0], [%1], 16;" \
                 :: "r"(dst), "l"(src) : "memory")
#define CP_COMMIT() asm volatile("cp.async.commit_group;" ::: "memory")
#define CP_WAIT0()  asm volatile("cp.async.wait_group 0;" ::: "memory")

// smem tile layout: 128 rows x 64 bf16 = 128B/row; SW128 xor swizzle.
#define OFF_AH 0
#define OFF_AL 16384
#define OFF_BH 32768
#define OFF_BL 49152
#define GEMM_SMEM 65536

// ---------------------------------------------------------------------------
// wsplit: W [128 x 256] fp32 -> hi/lo bf16, stored pre-swizzled per chunk.
// ---------------------------------------------------------------------------
__global__ __launch_bounds__(256) void wsplit_kernel(const float* __restrict__ W)
{
    int g  = blockIdx.x * blockDim.x + threadIdx.x;   // 0..4095
    int r  = g >> 5;
    int kg = g & 31;
    int c  = kg >> 3;
    const float* src = W + r * IN_F + kg * 8;
    float4 va = *(const float4*)(src);
    float4 vb = *(const float4*)(src + 4);
    float hax = __bfloat162float(__float2bfloat16_rn(va.x));
    float hay = __bfloat162float(__float2bfloat16_rn(va.y));
    float haz = __bfloat162float(__float2bfloat16_rn(va.z));
    float haw = __bfloat162float(__float2bfloat16_rn(va.w));
    float hbx = __bfloat162float(__float2bfloat16_rn(vb.x));
    float hby = __bfloat162float(__float2bfloat16_rn(vb.y));
    float hbz = __bfloat162float(__float2bfloat16_rn(vb.z));
    float hbw = __bfloat162float(__float2bfloat16_rn(vb.w));
    uint4 hi = make_uint4(pk_bf16(hax, hay), pk_bf16(haz, haw),
                          pk_bf16(hbx, hby), pk_bf16(hbz, hbw));
    uint4 lo = make_uint4(pk_bf16(va.x - hax, va.y - hay),
                          pk_bf16(va.z - haz, va.w - haw),
                          pk_bf16(vb.x - hbx, vb.y - hby),
                          pk_bf16(vb.z - hbz, vb.w - hbw));
    uint32_t off = (uint32_t)c * 16384 + r * 128 +
                   (((uint32_t)(kg & 7) * 16) ^ ((r & 7) << 4));
    *(uint4*)(g_Wh + off) = hi;
    *(uint4*)(g_Wl + off) = lo;
}

// ---------------------------------------------------------------------------
// GEMM: support = x @ W^T + b, bf16 split 3-pass mma.sync. fp16 epilogue.
// B tiles streamed via cp.async (overlaps with A split-convert ALU work).
// ---------------------------------------------------------------------------
__global__ __launch_bounds__(256, 2) void gcn_linear_mma_kernel(
    const float* __restrict__ x,
    const float* __restrict__ b,
    int n_nodes)
{
    extern __shared__ char smem[];
    const uint32_t sb = smem_to_u32(smem);
    const int t    = threadIdx.x;
    const int wid  = t >> 5;
    const int lane = t & 31;
    const int row0 = blockIdx.x * TILE_M;

    const int fr = t & 127;
    const int fh = t >> 7;
    const uint32_t frow_base = fr * 128;
    const uint32_t fxorm = (fr & 7) << 4;
    const bool a_valid = (row0 + fr) < n_nodes;

    const int wm = (wid & 3) * 32;
    const int wn = (wid >> 2) * 64;

    float acc[2][8][4];
#pragma unroll
    for (int mt = 0; mt < 2; mt++)
#pragma unroll
        for (int nt = 0; nt < 8; nt++)
#pragma unroll
            for (int j = 0; j < 4; j++) acc[mt][nt][j] = 0.0f;

    for (int c = 0; c < IN_F / KC; c++) {
        __syncthreads();
        // ---- B fill first: async copy of pre-swizzled W images ----
        {
            const char* srcH = (const char*)g_Wh + (size_t)c * 16384;
            const char* srcL = (const char*)g_Wl + (size_t)c * 16384;
#pragma unroll
            for (int i = 0; i < 4; i++) {
                uint32_t byteoff = (uint32_t)(t + i * 256) * 16;
                CP_ASYNC16(sb + OFF_BH + byteoff, srcH + byteoff);
                CP_ASYNC16(sb + OFF_BL + byteoff, srcL + byteoff);
            }
            CP_COMMIT();
        }
        // ---- A fill: split-convert x chunk (ALU work overlaps cp.async) ----
        const float* xs = x + (size_t)(row0 + fr) * IN_F + c * KC + fh * 32;
#pragma unroll
        for (int m = 0; m < 4; m++) {
            float4 va = a_valid ? *(const float4*)(xs + m * 8)
                                : make_float4(0.f, 0.f, 0.f, 0.f);
            float4 vb = a_valid ? *(const float4*)(xs + m * 8 + 4)
                                : make_float4(0.f, 0.f, 0.f, 0.f);
            uint32_t off = frow_base + ((uint32_t)(fh * 64 + m * 16) ^ fxorm);
            float hax = __bfloat162float(__float2bfloat16_rn(va.x));
            float hay = __bfloat162float(__float2bfloat16_rn(va.y));
            float haz = __bfloat162float(__float2bfloat16_rn(va.z));
            float haw = __bfloat162float(__float2bfloat16_rn(va.w));
            float hbx = __bfloat162float(__float2bfloat16_rn(vb.x));
            float hby = __bfloat162float(__float2bfloat16_rn(vb.y));
            float hbz = __bfloat162float(__float2bfloat16_rn(vb.z));
            float hbw = __bfloat162float(__float2bfloat16_rn(vb.w));
            uint4 hi = make_uint4(pk_bf16(hax, hay), pk_bf16(haz, haw),
                                  pk_bf16(hbx, hby), pk_bf16(hbz, hbw));
            uint4 lo = make_uint4(pk_bf16(va.x - hax, va.y - hay),
                                  pk_bf16(va.z - haz, va.w - haw),
                                  pk_bf16(vb.x - hbx, vb.y - hby),
                                  pk_bf16(vb.z - hbz, vb.w - hbw));
            *(uint4*)(smem + OFF_AH + off) = hi;
            *(uint4*)(smem + OFF_AL + off) = lo;
        }
        CP_WAIT0();
        __syncthreads();

#pragma unroll
        for (int ks = 0; ks < 4; ks++) {
            uint32_t ah[2][4], al[2][4];
#pragma unroll
            for (int mt = 0; mt < 2; mt++) {
                int row = wm + mt * 16 + (lane & 15);
                uint32_t cb = (uint32_t)(ks * 32 + ((lane >> 4) << 4));
                uint32_t off = row * 128 + (cb ^ ((row & 7) << 4));
                ldsm4(ah[mt], sb + OFF_AH + off);
                ldsm4(al[mt], sb + OFF_AL + off);
            }
#pragma unroll
            for (int ng = 0; ng < 4; ng++) {
                int nrow = wn + ng * 16 + (lane & 7) + ((lane >> 4) << 3);
                uint32_t cb = (uint32_t)(ks * 32 + (((lane >> 3) & 1) << 4));
                uint32_t off = nrow * 128 + (cb ^ ((nrow & 7) << 4));
                uint32_t bh[4], bl[4];
                ldsm4(bh, sb + OFF_BH + off);
                ldsm4(bl, sb + OFF_BL + off);
#pragma unroll
                for (int sub = 0; sub < 2; sub++) {
                    int nt = ng * 2 + sub;
#pragma unroll
                    for (int mt = 0; mt < 2; mt++) {
                        mma16816(acc[mt][nt], ah[mt], bh + sub * 2);
                        mma16816(acc[mt][nt], ah[mt], bl + sub * 2);
                        mma16816(acc[mt][nt], al[mt], bh + sub * 2);
                    }
                }
            }
        }
    }

    // ---- epilogue: bias + fp16 store ----
#pragma unroll
    for (int nt = 0; nt < 8; nt++) {
        int col = wn + nt * 8 + 2 * (lane & 3);
        float2 bb = *(const float2*)(b + col);
#pragma unroll
        for (int mt = 0; mt < 2; mt++) {
            int r0g = row0 + wm + mt * 16 + (lane >> 2);
            if (r0g < n_nodes) {
                __half2 h0 = __floats2half2_rn(acc[mt][nt][0] + bb.x,
                                               acc[mt][nt][1] + bb.y);
                *(__half2*)(g_support_h + (size_t)r0g * HID + col) = h0;
            }
            int r1g = r0g + 8;
            if (r1g < n_nodes) {
                __half2 h1 = __floats2half2_rn(acc[mt][nt][2] + bb.x,
                                               acc[mt][nt][3] + bb.y);
                *(__half2*)(g_support_h + (size_t)r1g * HID + col) = h1;
            }
        }
    }
}

// ---------------------------------------------------------------------------
// hist: int4-vectorized edge histogram (4 edges/thread)
// ---------------------------------------------------------------------------
__global__ __launch_bounds__(256) void hist_kernel(
    const int* __restrict__ adj_row, int n_edges)
{
    int base = (blockIdx.x * blockDim.x + threadIdx.x) * 4;
    if (base + 3 < n_edges) {
        int4 r = *(const int4*)(adj_row + base);
        atomicAdd(&g_cnt[r.x], 1);
        atomicAdd(&g_cnt[r.y], 1);
        atomicAdd(&g_cnt[r.z], 1);
        atomicAdd(&g_cnt[r.w], 1);
    } else {
        for (int e = base; e < n_edges; e++)
            atomicAdd(&g_cnt[adj_row[e]], 1);
    }
}

// scan_a: per-block reduce of g_cnt (256/block) -> g_bsum
__global__ __launch_bounds__(SCAN_B) void scan_a_kernel(int n_nodes)
{
    __shared__ int sm[SCAN_B / 32];
    const int t   = threadIdx.x;
    const int idx = blockIdx.x * SCAN_B + t;
    int v = (idx < n_nodes) ? g_cnt[idx] : 0;
#pragma unroll
    for (int o = 16; o > 0; o >>= 1) v += __shfl_down_sync(0xffffffffu, v, o);
    if ((t & 31) == 0) sm[t >> 5] = v;
    __syncthreads();
    if (t < 32) {
        int s = (t < SCAN_B / 32) ? sm[t] : 0;
#pragma unroll
        for (int o = 4; o > 0; o >>= 1) s += __shfl_down_sync(0xffffffffu, s, o);
        if (t == 0) g_bsum[blockIdx.x] = s;
    }
}

// scan_c: block prefix from g_bsum + local scan; re-zeroes g_cnt.
__global__ __launch_bounds__(SCAN_B) void scan_c_kernel(int n_sb, int n_nodes)
{
    __shared__ int bs[SCAN_B];
    __shared__ int sm[SCAN_B];
    const int t   = threadIdx.x;
    const int idx = blockIdx.x * SCAN_B + t;

    int bv = (t < n_sb) ? g_bsum[t] : 0;
    bs[t] = bv;
    __syncthreads();
#pragma unroll
    for (int o = 1; o < SCAN_B; o <<= 1) {
        int u = (t >= o) ? bs[t - o] : 0;
        __syncthreads();
        bs[t] += u;
        __syncthreads();
    }
    const int blk_prefix = (blockIdx.x > 0) ? bs[blockIdx.x - 1] : 0;
    if (blockIdx.x == 0 && t == 0) g_row_start[n_nodes] = bs[n_sb - 1];

    int v = (idx < n_nodes) ? g_cnt[idx] : 0;
    sm[t] = v;
    __syncthreads();
#pragma unroll
    for (int o = 1; o < SCAN_B; o <<= 1) {
        int u = (t >= o) ? sm[t - o] : 0;
        __syncthreads();
        sm[t] += u;
        __syncthreads();
    }
    if (idx < n_nodes) {
        int excl = blk_prefix + sm[t] - v;
        g_row_start[idx] = excl;
        g_cursor[idx]    = excl;
        g_cnt[idx]       = 0;
    }
}

// fill: int4-vectorized (4 edges/thread, independent atomic chains)
__global__ __launch_bounds__(256) void fill_kernel(
    const int*   __restrict__ adj_row,
    const int*   __restrict__ adj_col,
    const float* __restrict__ adj_val,
    int n_edges)
{
    int base = (blockIdx.x * blockDim.x + threadIdx.x) * 4;
    if (base + 3 < n_edges) {
        int4   r = *(const int4*)(adj_row + base);
        int4   c = *(const int4*)(adj_col + base);
        float4 v = *(const float4*)(adj_val + base);
        int p0 = atomicAdd(&g_cursor[r.x], 1);
        int p1 = atomicAdd(&g_cursor[r.y], 1);
        int p2 = atomicAdd(&g_cursor[r.z], 1);
        int p3 = atomicAdd(&g_cursor[r.w], 1);
        g_edge[p0] = make_int2(c.x, __float_as_int(v.x));
        g_edge[p1] = make_int2(c.y, __float_as_int(v.y));
        g_edge[p2] = make_int2(c.z, __float_as_int(v.z));
        g_edge[p3] = make_int2(c.w, __float_as_int(v.w));
    } else {
        for (int e = base; e < n_edges; e++) {
            int r   = adj_row[e];
            int pos = atomicAdd(&g_cursor[r], 1);
            g_edge[pos] = make_int2(adj_col[e], __float_as_int(adj_val[e]));
        }
    }
}

// ---------------------------------------------------------------------------
// gather: warp per row, HALF-WARP per edge. 16 lanes x uint4 = one 256B
// support row; a warp processes 2 edges per load instruction. shfl_xor(16)
// butterfly merges halves; lanes 0-15 write 2 float4 each.
// ---------------------------------------------------------------------------
__global__ __launch_bounds__(256) void row_gather_kernel(
    float* __restrict__ out, int n_nodes)
{
    const int row  = (blockIdx.x * blockDim.x + threadIdx.x) >> 5;
    const int lane = threadIdx.x & 31;
    const int half = lane >> 4;           // 0 or 1
    const int hl   = lane & 15;           // lane within half
    if (row >= n_nodes) return;

    const int s0 = g_row_start[row];
    const int s1 = g_row_start[row + 1];

    const uint4* sup = reinterpret_cast<const uint4*>(g_support_h); // 16/row
    float acc[8];
#pragma unroll
    for (int j = 0; j < 8; j++) acc[j] = 0.0f;

    int e = s0 + half;
    // unroll-2: two edges in flight per half-warp
    for (; e + 2 < s1; e += 4) {
        int2 ev0 = g_edge[e];
        int2 ev1 = g_edge[e + 2];
        uint4 r0 = sup[(size_t)ev0.x * 16 + hl];
        uint4 r1 = sup[(size_t)ev1.x * 16 + hl];
        float v0 = __int_as_float(ev0.y);
        float v1 = __int_as_float(ev1.y);
        float2 p0 = __half22float2(*(const __half2*)&r0.x);
        float2 p1 = __half22float2(*(const __half2*)&r0.y);
        float2 p2 = __half22float2(*(const __half2*)&r0.z);
        float2 p3 = __half22float2(*(const __half2*)&r0.w);
        float2 q0 = __half22float2(*(const __half2*)&r1.x);
        float2 q1 = __half22float2(*(const __half2*)&r1.y);
        float2 q2 = __half22float2(*(const __half2*)&r1.z);
        float2 q3 = __half22float2(*(const __half2*)&r1.w);
        acc[0] += v0 * p0.x + v1 * q0.x;
        acc[1] += v0 * p0.y + v1 * q0.y;
        acc[2] += v0 * p1.x + v1 * q1.x;
        acc[3] += v0 * p1.y + v1 * q1.y;
        acc[4] += v0 * p2.x + v1 * q2.x;
        acc[5] += v0 * p2.y + v1 * q2.y;
        acc[6] += v0 * p3.x + v1 * q3.x;
        acc[7] += v0 * p3.y + v1 * q3.y;
    }
    for (; e < s1; e += 2) {
        int2 ev = g_edge[e];
        uint4 r0 = sup[(size_t)ev.x * 16 + hl];
        float v = __int_as_float(ev.y);
        float2 p0 = __half22float2(*(const __half2*)&r0.x);
        float2 p1 = __half22float2(*(const __half2*)&r0.y);
        float2 p2 = __half22float2(*(const __half2*)&r0.z);
        float2 p3 = __half22float2(*(const __half2*)&r0.w);
        acc[0] += v * p0.x; acc[1] += v * p0.y;
        acc[2] += v * p1.x; acc[3] += v * p1.y;
        acc[4] += v * p2.x; acc[5] += v * p2.y;
        acc[6] += v * p3.x; acc[7] += v * p3.y;
    }

    // merge the two half-warps (lane i <-> lane i+16 hold same dims)
#pragma unroll
    for (int j = 0; j < 8; j++)
        acc[j] += __shfl_xor_sync(0xffffffffu, acc[j], 16);

    if (half == 0) {
        float4* o = reinterpret_cast<float4*>(out + (size_t)row * HID + hl * 8);
        o[0] = make_float4(acc[0], acc[1], acc[2], acc[3]);
        o[1] = make_float4(acc[4], acc[5], acc[6], acc[7]);
    }
}

// ---------------------------------------------------------------------------
// Side stream + events, created ONCE (no device-mem allocation APIs).
// ---------------------------------------------------------------------------
struct AuxStreams {
    cudaStream_t s  = nullptr;
    cudaEvent_t  e1 = nullptr, e2 = nullptr;
    bool ok = false;
    AuxStreams() {
        if (cudaStreamCreateWithFlags(&s, cudaStreamNonBlocking) != cudaSuccess) { s = nullptr; return; }
        if (cudaEventCreateWithFlags(&e1, cudaEventDisableTiming) != cudaSuccess) { e1 = nullptr; return; }
        if (cudaEventCreateWithFlags(&e2, cudaEventDisableTiming) != cudaSuccess) { e2 = nullptr; return; }
        ok = true;
    }
};
static AuxStreams g_aux;

// ---------------------------------------------------------------------------
// Launch: inputs: x, adj_row, adj_col, adj_val, W, b
// Graph:  main: wsplit -> gemm ----------------.-> gather
//         side: hist -> scan_a -> scan_c -> fill'
// ---------------------------------------------------------------------------
extern "C" void kernel_launch(void* const* d_in, const int* in_sizes, int n_in,
                              void* d_out, int out_size)
{
    const float* x       = (const float*)d_in[0];
    const int*   adj_row = (const int*)  d_in[1];
    const int*   adj_col = (const int*)  d_in[2];
    const float* adj_val = (const float*)d_in[3];
    const float* W       = (const float*)d_in[4];
    const float* b       = (const float*)d_in[5];
    float*       out     = (float*)d_out;

    const int n_nodes = in_sizes[0] / IN_F;
    const int n_edges = in_sizes[1];
    const int n_sb    = (n_nodes + SCAN_B - 1) / SCAN_B;
    const int gemm_blocks = (n_nodes + TILE_M - 1) / TILE_M;

    cudaFuncSetAttribute(gcn_linear_mma_kernel,
                         cudaFuncAttributeMaxDynamicSharedMemorySize, GEMM_SMEM);

    const bool par = g_aux.ok;
    cudaStream_t sbin = par ? g_aux.s : (cudaStream_t)0;

    if (par) {
        cudaEventRecord(g_aux.e1, 0);
        cudaStreamWaitEvent(sbin, g_aux.e1, 0);
    }

    wsplit_kernel<<<16, 256>>>(W);
    gcn_linear_mma_kernel<<<gemm_blocks, 256, GEMM_SMEM>>>(x, b, n_nodes);

    hist_kernel<<<(n_edges / 4 + 255) / 256, 256, 0, sbin>>>(adj_row, n_edges);
    scan_a_kernel<<<n_sb, SCAN_B, 0, sbin>>>(n_nodes);
    scan_c_kernel<<<n_sb, SCAN_B, 0, sbin>>>(n_sb, n_nodes);
    fill_kernel<<<(n_edges / 4 + 255) / 256, 256, 0, sbin>>>(adj_row, adj_col, adj_val, n_edges);

    if (par) {
        cudaEventRecord(g_aux.e2, sbin);
        cudaStreamWaitEvent(0, g_aux.e2, 0);
    }

    row_gather_kernel<<<(n_nodes * 32 + 255) / 256, 256>>>(out, n_nodes);
}

// round 10
// speedup vs baseline: 4.3166x; 1.0674x over previous
#include <cuda_runtime.h>
#include <cuda_bf16.h>
#include <cuda_fp16.h>
#include <cstdint>

#define IN_F 256
#define HID  128
#define TILE_M 128
#define MAX_NODES 50000
#define MAX_EDGES 800000
#define SCAN_B   256
#define ASTRIDE  68               // smem row stride in floats (bank-conflict-free)

// Scratch (device globals; no device-memory allocation APIs anywhere).
// INVARIANT: g_cnt is all-zero at kernel_launch entry; scan_c re-zeroes it.
__device__ __half g_support_h[MAX_NODES * HID];   // fp16 support
__device__ int    g_cnt[MAX_NODES];
__device__ int    g_row_start[MAX_NODES + 1];
__device__ int    g_cursor[MAX_NODES];
__device__ int2   g_edge[MAX_EDGES];
__device__ int    g_bsum[SCAN_B];
__device__ float  g_Wt[HID * IN_F];               // W pre-rounded to tf32 values

// ---------------------------------------------------------------------------
// Helpers (plain sm_80-era PTX; nothing arch-'a' gated)
// ---------------------------------------------------------------------------
__device__ __forceinline__ uint32_t smem_to_u32(const void* p) {
    uint32_t a;
    asm("{ .reg .u64 t; cvta.to.shared.u64 t, %1; cvt.u32.u64 %0, t; }"
        : "=r"(a) : "l"(p));
    return a;
}

__device__ __forceinline__ uint32_t f2tf32(float f) {
    uint32_t r;
    asm("cvt.rna.tf32.f32 %0, %1;" : "=r"(r) : "f"(f));
    return r;
}

__device__ __forceinline__ void mma_tf32(float* c, const uint32_t* a,
                                         uint32_t b0, uint32_t b1) {
    asm volatile("mma.sync.aligned.m16n8k8.row.col.f32.tf32.tf32.f32 "
        "{%0,%1,%2,%3}, {%4,%5,%6,%7}, {%8,%9}, {%0,%1,%2,%3};"
        : "+f"(c[0]), "+f"(c[1]), "+f"(c[2]), "+f"(c[3])
        : "r"(a[0]), "r"(a[1]), "r"(a[2]), "r"(a[3]), "r"(b0), "r"(b1));
}

#define CP_ASYNC16(dst, src) \
    asm volatile("cp.async.cg.shared.global [%0], [%1], 16;" \
                 :: "r"(dst), "l"(src) : "memory")
#define CP_ASYNC16G(dst, src, sz) \
    asm volatile("cp.async.cg.shared.global [%0], [%1], 16, %2;" \
                 :: "r"(dst), "l"(src), "r"(sz) : "memory")
#define CP_COMMIT() asm volatile("cp.async.commit_group;" ::: "memory")
#define CP_WAIT0()  asm volatile("cp.async.wait_group 0;" ::: "memory")

#define A_BYTES (TILE_M * ASTRIDE * 4)     // 34816
#define GEMM_SMEM (2 * A_BYTES)            // 69632

// ---------------------------------------------------------------------------
// wtf32: round W to tf32 (rna) once; plain [n][k] layout.
// ---------------------------------------------------------------------------
__global__ __launch_bounds__(256) void wtf32_kernel(const float* __restrict__ W)
{
    int i = (blockIdx.x * blockDim.x + threadIdx.x) * 4;   // 32 blocks
    float4 v = *(const float4*)(W + i);
    uint4 r;
    r.x = f2tf32(v.x); r.y = f2tf32(v.y);
    r.z = f2tf32(v.z); r.w = f2tf32(v.w);
    *(uint4*)(g_Wt + i) = r;
}

// ---------------------------------------------------------------------------
// GEMM: support = x @ W^T + b via single-pass tf32 mma (m16n8k8).
// A, B tiles streamed raw via cp.async; A cvt to tf32 at use.
// ---------------------------------------------------------------------------
__global__ __launch_bounds__(256, 2) void gcn_linear_tf32_kernel(
    const float* __restrict__ x,
    const float* __restrict__ b,
    int n_nodes)
{
    extern __shared__ char smem[];
    float* As = (float*)smem;
    float* Bs = (float*)(smem + A_BYTES);
    const uint32_t sbA = smem_to_u32(As);
    const uint32_t sbB = smem_to_u32(Bs);

    const int t    = threadIdx.x;
    const int wid  = t >> 5;
    const int lane = t & 31;
    const int gid  = lane >> 2;          // 0..7
    const int tig  = lane & 3;           // 0..3
    const int row0 = blockIdx.x * TILE_M;

    const int wm = (wid & 3) * 32;
    const int wn = (wid >> 2) * 64;

    float acc[2][8][4];
#pragma unroll
    for (int mt = 0; mt < 2; mt++)
#pragma unroll
        for (int nt = 0; nt < 8; nt++)
#pragma unroll
            for (int j = 0; j < 4; j++) acc[mt][nt][j] = 0.0f;

    for (int c = 0; c < IN_F / 64; c++) {      // 4 K-chunks of 64
        __syncthreads();
        // ---- fill A (x rows, raw fp32) and B (g_Wt rows) via cp.async ----
#pragma unroll
        for (int i = 0; i < 8; i++) {
            int idx = t + i * 256;              // 0..2047
            int n   = idx >> 4;                 // tile row 0..127
            int kq  = idx & 15;                 // float4 group 0..15
            uint32_t doff = (uint32_t)(n * ASTRIDE + kq * 4) * 4;
            int grow = row0 + n;
            const float* asrc = x + (size_t)grow * IN_F + c * 64 + kq * 4;
            int asz = (grow < n_nodes) ? 16 : 0;
            CP_ASYNC16G(sbA + doff, asrc, asz);
            const float* bsrc = g_Wt + n * IN_F + c * 64 + kq * 4;
            CP_ASYNC16(sbB + doff, bsrc);
        }
        CP_COMMIT();
        CP_WAIT0();
        __syncthreads();

#pragma unroll
        for (int ks = 0; ks < 8; ks++) {        // 8 K8 steps
            uint32_t a[2][4];
#pragma unroll
            for (int mt = 0; mt < 2; mt++) {
                int r0 = wm + mt * 16 + gid;
                int kc = ks * 8 + tig;
                a[mt][0] = f2tf32(As[r0 * ASTRIDE + kc]);
                a[mt][1] = f2tf32(As[(r0 + 8) * ASTRIDE + kc]);
                a[mt][2] = f2tf32(As[r0 * ASTRIDE + kc + 4]);
                a[mt][3] = f2tf32(As[(r0 + 8) * ASTRIDE + kc + 4]);
            }
#pragma unroll
            for (int ng = 0; ng < 8; ng++) {
                int nr = wn + ng * 8 + gid;
                int kc = ks * 8 + tig;
                uint32_t b0 = __float_as_uint(Bs[nr * ASTRIDE + kc]);
                uint32_t b1 = __float_as_uint(Bs[nr * ASTRIDE + kc + 4]);
                mma_tf32(acc[0][ng], a[0], b0, b1);
                mma_tf32(acc[1][ng], a[1], b0, b1);
            }
        }
    }

    // ---- epilogue: bias + fp16 store (C frag: rows gid/gid+8, cols 2*tig) ----
#pragma unroll
    for (int nt = 0; nt < 8; nt++) {
        int col = wn + nt * 8 + 2 * tig;
        float2 bb = *(const float2*)(b + col);
#pragma unroll
        for (int mt = 0; mt < 2; mt++) {
            int r0g = row0 + wm + mt * 16 + gid;
            if (r0g < n_nodes) {
                __half2 h0 = __floats2half2_rn(acc[mt][nt][0] + bb.x,
                                               acc[mt][nt][1] + bb.y);
                *(__half2*)(g_support_h + (size_t)r0g * HID + col) = h0;
            }
            int r1g = r0g + 8;
            if (r1g < n_nodes) {
                __half2 h1 = __floats2half2_rn(acc[mt][nt][2] + bb.x,
                                               acc[mt][nt][3] + bb.y);
                *(__half2*)(g_support_h + (size_t)r1g * HID + col) = h1;
            }
        }
    }
}

// ---------------------------------------------------------------------------
// hist: int4-vectorized edge histogram (4 edges/thread)
// ---------------------------------------------------------------------------
__global__ __launch_bounds__(256) void hist_kernel(
    const int* __restrict__ adj_row, int n_edges)
{
    int base = (blockIdx.x * blockDim.x + threadIdx.x) * 4;
    if (base + 3 < n_edges) {
        int4 r = *(const int4*)(adj_row + base);
        atomicAdd(&g_cnt[r.x], 1);
        atomicAdd(&g_cnt[r.y], 1);
        atomicAdd(&g_cnt[r.z], 1);
        atomicAdd(&g_cnt[r.w], 1);
    } else {
        for (int e = base; e < n_edges; e++)
            atomicAdd(&g_cnt[adj_row[e]], 1);
    }
}

// scan_a: per-block reduce of g_cnt (256/block) -> g_bsum
__global__ __launch_bounds__(SCAN_B) void scan_a_kernel(int n_nodes)
{
    __shared__ int sm[SCAN_B / 32];
    const int t   = threadIdx.x;
    const int idx = blockIdx.x * SCAN_B + t;
    int v = (idx < n_nodes) ? g_cnt[idx] : 0;
#pragma unroll
    for (int o = 16; o > 0; o >>= 1) v += __shfl_down_sync(0xffffffffu, v, o);
    if ((t & 31) == 0) sm[t >> 5] = v;
    __syncthreads();
    if (t < 32) {
        int s = (t < SCAN_B / 32) ? sm[t] : 0;
#pragma unroll
        for (int o = 4; o > 0; o >>= 1) s += __shfl_down_sync(0xffffffffu, s, o);
        if (t == 0) g_bsum[blockIdx.x] = s;
    }
}

// scan_c: block prefix from g_bsum + local scan; re-zeroes g_cnt.
__global__ __launch_bounds__(SCAN_B) void scan_c_kernel(int n_sb, int n_nodes)
{
    __shared__ int bs[SCAN_B];
    __shared__ int sm[SCAN_B];
    const int t   = threadIdx.x;
    const int idx = blockIdx.x * SCAN_B + t;

    int bv = (t < n_sb) ? g_bsum[t] : 0;
    bs[t] = bv;
    __syncthreads();
#pragma unroll
    for (int o = 1; o < SCAN_B; o <<= 1) {
        int u = (t >= o) ? bs[t - o] : 0;
        __syncthreads();
        bs[t] += u;
        __syncthreads();
    }
    const int blk_prefix = (blockIdx.x > 0) ? bs[blockIdx.x - 1] : 0;
    if (blockIdx.x == 0 && t == 0) g_row_start[n_nodes] = bs[n_sb - 1];

    int v = (idx < n_nodes) ? g_cnt[idx] : 0;
    sm[t] = v;
    __syncthreads();
#pragma unroll
    for (int o = 1; o < SCAN_B; o <<= 1) {
        int u = (t >= o) ? sm[t - o] : 0;
        __syncthreads();
        sm[t] += u;
        __syncthreads();
    }
    if (idx < n_nodes) {
        int excl = blk_prefix + sm[t] - v;
        g_row_start[idx] = excl;
        g_cursor[idx]    = excl;
        g_cnt[idx]       = 0;
    }
}

// fill: int4-vectorized (4 edges/thread, independent atomic chains)
__global__ __launch_bounds__(256) void fill_kernel(
    const int*   __restrict__ adj_row,
    const int*   __restrict__ adj_col,
    const float* __restrict__ adj_val,
    int n_edges)
{
    int base = (blockIdx.x * blockDim.x + threadIdx.x) * 4;
    if (base + 3 < n_edges) {
        int4   r = *(const int4*)(adj_row + base);
        int4   c = *(const int4*)(adj_col + base);
        float4 v = *(const float4*)(adj_val + base);
        int p0 = atomicAdd(&g_cursor[r.x], 1);
        int p1 = atomicAdd(&g_cursor[r.y], 1);
        int p2 = atomicAdd(&g_cursor[r.z], 1);
        int p3 = atomicAdd(&g_cursor[r.w], 1);
        g_edge[p0] = make_int2(c.x, __float_as_int(v.x));
        g_edge[p1] = make_int2(c.y, __float_as_int(v.y));
        g_edge[p2] = make_int2(c.z, __float_as_int(v.z));
        g_edge[p3] = make_int2(c.w, __float_as_int(v.w));
    } else {
        for (int e = base; e < n_edges; e++) {
            int r   = adj_row[e];
            int pos = atomicAdd(&g_cursor[r], 1);
            g_edge[pos] = make_int2(adj_col[e], __float_as_int(adj_val[e]));
        }
    }
}

// ---------------------------------------------------------------------------
// gather: warp per row, half-warp per edge (16 lanes x uint4 = 256B row),
// shfl_xor(16) merge, no atomics.
// ---------------------------------------------------------------------------
__global__ __launch_bounds__(256) void row_gather_kernel(
    float* __restrict__ out, int n_nodes)
{
    const int row  = (blockIdx.x * blockDim.x + threadIdx.x) >> 5;
    const int lane = threadIdx.x & 31;
    const int half = lane >> 4;
    const int hl   = lane & 15;
    if (row >= n_nodes) return;

    const int s0 = g_row_start[row];
    const int s1 = g_row_start[row + 1];

    const uint4* sup = reinterpret_cast<const uint4*>(g_support_h);
    float acc[8];
#pragma unroll
    for (int j = 0; j < 8; j++) acc[j] = 0.0f;

    int e = s0 + half;
    for (; e + 2 < s1; e += 4) {
        int2 ev0 = g_edge[e];
        int2 ev1 = g_edge[e + 2];
        uint4 r0 = sup[(size_t)ev0.x * 16 + hl];
        uint4 r1 = sup[(size_t)ev1.x * 16 + hl];
        float v0 = __int_as_float(ev0.y);
        float v1 = __int_as_float(ev1.y);
        float2 p0 = __half22float2(*(const __half2*)&r0.x);
        float2 p1 = __half22float2(*(const __half2*)&r0.y);
        float2 p2 = __half22float2(*(const __half2*)&r0.z);
        float2 p3 = __half22float2(*(const __half2*)&r0.w);
        float2 q0 = __half22float2(*(const __half2*)&r1.x);
        float2 q1 = __half22float2(*(const __half2*)&r1.y);
        float2 q2 = __half22float2(*(const __half2*)&r1.z);
        float2 q3 = __half22float2(*(const __half2*)&r1.w);
        acc[0] += v0 * p0.x + v1 * q0.x;
        acc[1] += v0 * p0.y + v1 * q0.y;
        acc[2] += v0 * p1.x + v1 * q1.x;
        acc[3] += v0 * p1.y + v1 * q1.y;
        acc[4] += v0 * p2.x + v1 * q2.x;
        acc[5] += v0 * p2.y + v1 * q2.y;
        acc[6] += v0 * p3.x + v1 * q3.x;
        acc[7] += v0 * p3.y + v1 * q3.y;
    }
    for (; e < s1; e += 2) {
        int2 ev = g_edge[e];
        uint4 r0 = sup[(size_t)ev.x * 16 + hl];
        float v = __int_as_float(ev.y);
        float2 p0 = __half22float2(*(const __half2*)&r0.x);
        float2 p1 = __half22float2(*(const __half2*)&r0.y);
        float2 p2 = __half22float2(*(const __half2*)&r0.z);
        float2 p3 = __half22float2(*(const __half2*)&r0.w);
        acc[0] += v * p0.x; acc[1] += v * p0.y;
        acc[2] += v * p1.x; acc[3] += v * p1.y;
        acc[4] += v * p2.x; acc[5] += v * p2.y;
        acc[6] += v * p3.x; acc[7] += v * p3.y;
    }

#pragma unroll
    for (int j = 0; j < 8; j++)
        acc[j] += __shfl_xor_sync(0xffffffffu, acc[j], 16);

    if (half == 0) {
        float4* o = reinterpret_cast<float4*>(out + (size_t)row * HID + hl * 8);
        o[0] = make_float4(acc[0], acc[1], acc[2], acc[3]);
        o[1] = make_float4(acc[4], acc[5], acc[6], acc[7]);
    }
}

// ---------------------------------------------------------------------------
// Side stream + events, created ONCE (no device-mem allocation APIs).
// ---------------------------------------------------------------------------
struct AuxStreams {
    cudaStream_t s  = nullptr;
    cudaEvent_t  e1 = nullptr, e2 = nullptr;
    bool ok = false;
    AuxStreams() {
        if (cudaStreamCreateWithFlags(&s, cudaStreamNonBlocking) != cudaSuccess) { s = nullptr; return; }
        if (cudaEventCreateWithFlags(&e1, cudaEventDisableTiming) != cudaSuccess) { e1 = nullptr; return; }
        if (cudaEventCreateWithFlags(&e2, cudaEventDisableTiming) != cudaSuccess) { e2 = nullptr; return; }
        ok = true;
    }
};
static AuxStreams g_aux;

// ---------------------------------------------------------------------------
// Launch: inputs: x, adj_row, adj_col, adj_val, W, b
// Graph:  main: wtf32 -> gemm ----------------.-> gather
//         side: hist -> scan_a -> scan_c -> fill'
// ---------------------------------------------------------------------------
extern "C" void kernel_launch(void* const* d_in, const int* in_sizes, int n_in,
                              void* d_out, int out_size)
{
    const float* x       = (const float*)d_in[0];
    const int*   adj_row = (const int*)  d_in[1];
    const int*   adj_col = (const int*)  d_in[2];
    const float* adj_val = (const float*)d_in[3];
    const float* W       = (const float*)d_in[4];
    const float* b       = (const float*)d_in[5];
    float*       out     = (float*)d_out;

    const int n_nodes = in_sizes[0] / IN_F;
    const int n_edges = in_sizes[1];
    const int n_sb    = (n_nodes + SCAN_B - 1) / SCAN_B;
    const int gemm_blocks = (n_nodes + TILE_M - 1) / TILE_M;

    cudaFuncSetAttribute(gcn_linear_tf32_kernel,
                         cudaFuncAttributeMaxDynamicSharedMemorySize, GEMM_SMEM);

    const bool par = g_aux.ok;
    cudaStream_t sbin = par ? g_aux.s : (cudaStream_t)0;

    if (par) {
        cudaEventRecord(g_aux.e1, 0);
        cudaStreamWaitEvent(sbin, g_aux.e1, 0);
    }

    wtf32_kernel<<<32, 256>>>(W);
    gcn_linear_tf32_kernel<<<gemm_blocks, 256, GEMM_SMEM>>>(x, b, n_nodes);

    hist_kernel<<<(n_edges / 4 + 255) / 256, 256, 0, sbin>>>(adj_row, n_edges);
    scan_a_kernel<<<n_sb, SCAN_B, 0, sbin>>>(n_nodes);
    scan_c_kernel<<<n_sb, SCAN_B, 0, sbin>>>(n_sb, n_nodes);
    fill_kernel<<<(n_edges / 4 + 255) / 256, 256, 0, sbin>>>(adj_row, adj_col, adj_val, n_edges);

    if (par) {
        cudaEventRecord(g_aux.e2, sbin);
        cudaStreamWaitEvent(0, g_aux.e2, 0);
    }

    row_gather_kernel<<<(n_nodes * 32 + 255) / 256, 256>>>(out, n_nodes);
}

// round 11
// speedup vs baseline: 4.4710x; 1.0358x over previous
#include <cuda_runtime.h>
#include <cuda_bf16.h>
#include <cuda_fp16.h>
#include <cstdint>

#define IN_F 256
#define HID  128
#define TILE_M 128
#define MAX_NODES 50000
#define MAX_EDGES 800000
#define SCAN_B   256
#define KCH      32               // K per pipeline stage
#define NCH      (IN_F / KCH)     // 8 stages
#define SSTRIDE  36               // smem row stride in floats (36 % 32 == 4)

// Scratch (device globals; no device-memory allocation APIs anywhere).
// INVARIANT: g_cnt is all-zero at kernel_launch entry; scan_c re-zeroes it.
__device__ __half g_support_h[MAX_NODES * HID];   // fp16 support
__device__ int    g_cnt[MAX_NODES];
__device__ int    g_row_start[MAX_NODES + 1];
__device__ int    g_cursor[MAX_NODES];
__device__ int2   g_edge[MAX_EDGES];
__device__ int    g_bsum[SCAN_B];
__device__ float  g_Wt[HID * IN_F];               // W pre-rounded to tf32 values

// ---------------------------------------------------------------------------
// Helpers (plain sm_80-era PTX; nothing arch-'a' gated)
// ---------------------------------------------------------------------------
__device__ __forceinline__ uint32_t smem_to_u32(const void* p) {
    uint32_t a;
    asm("{ .reg .u64 t; cvta.to.shared.u64 t, %1; cvt.u32.u64 %0, t; }"
        : "=r"(a) : "l"(p));
    return a;
}

__device__ __forceinline__ uint32_t f2tf32(float f) {
    uint32_t r;
    asm("cvt.rna.tf32.f32 %0, %1;" : "=r"(r) : "f"(f));
    return r;
}

__device__ __forceinline__ void mma_tf32(float* c, const uint32_t* a,
                                         uint32_t b0, uint32_t b1) {
    asm volatile("mma.sync.aligned.m16n8k8.row.col.f32.tf32.tf32.f32 "
        "{%0,%1,%2,%3}, {%4,%5,%6,%7}, {%8,%9}, {%0,%1,%2,%3};"
        : "+f"(c[0]), "+f"(c[1]), "+f"(c[2]), "+f"(c[3])
        : "r"(a[0]), "r"(a[1]), "r"(a[2]), "r"(a[3]), "r"(b0), "r"(b1));
}

#define CP_ASYNC16(dst, src) \
    asm volatile("cp.async.cg.shared.global [%0], [%1], 16;" \
                 :: "r"(dst), "l"(src) : "memory")
#define CP_ASYNC16G(dst, src, sz) \
    asm volatile("cp.async.cg.shared.global [%0], [%1], 16, %2;" \
                 :: "r"(dst), "l"(src), "r"(sz) : "memory")
#define CP_COMMIT() asm volatile("cp.async.commit_group;" ::: "memory")
#define CP_WAIT(n)  asm volatile("cp.async.wait_group %0;" :: "n"(n) : "memory")

#define HALF_STAGE (TILE_M * SSTRIDE * 4)     // 18432 B (one of A or B)
#define STAGE_BYTES (2 * HALF_STAGE)          // 36864 B (A + B)
#define GEMM_SMEM (2 * STAGE_BYTES)           // 73728 B, occ 2 -> 147KB/SM

// ---------------------------------------------------------------------------
// wtf32: round W to tf32 (rna) once; plain [n][k] layout.
// ---------------------------------------------------------------------------
__global__ __launch_bounds__(256) void wtf32_kernel(const float* __restrict__ W)
{
    int i = (blockIdx.x * blockDim.x + threadIdx.x) * 4;   // 32 blocks
    float4 v = *(const float4*)(W + i);
    uint4 r;
    r.x = f2tf32(v.x); r.y = f2tf32(v.y);
    r.z = f2tf32(v.z); r.w = f2tf32(v.w);
    *(uint4*)(g_Wt + i) = r;
}

// ---------------------------------------------------------------------------
// GEMM: support = x @ W^T + b via single-pass tf32 mma (m16n8k8),
// two-stage cp.async pipeline over 8 K-chunks of 32.
// ---------------------------------------------------------------------------
__global__ __launch_bounds__(256, 2) void gcn_linear_tf32_kernel(
    const float* __restrict__ x,
    const float* __restrict__ b,
    int n_nodes)
{
    extern __shared__ char smem[];
    const uint32_t sbase = smem_to_u32(smem);

    const int t    = threadIdx.x;
    const int wid  = t >> 5;
    const int lane = t & 31;
    const int gid  = lane >> 2;          // 0..7
    const int tig  = lane & 3;           // 0..3
    const int row0 = blockIdx.x * TILE_M;

    const int wm = (wid & 3) * 32;
    const int wn = (wid >> 2) * 64;

    // fill role: 8 cp.async per thread per chunk (4 A + 4 B)
    const int fn = t >> 1;               // row handled for fills (2 thr/row... )
    (void)fn;

    float acc[2][8][4];
#pragma unroll
    for (int mt = 0; mt < 2; mt++)
#pragma unroll
        for (int nt = 0; nt < 8; nt++)
#pragma unroll
            for (int j = 0; j < 4; j++) acc[mt][nt][j] = 0.0f;

    // issue loads for chunk c into stage s
    auto issue = [&](int c, int s) {
        uint32_t aBase = sbase + (uint32_t)s * STAGE_BYTES;
        uint32_t bBase = aBase + HALF_STAGE;
#pragma unroll
        for (int i = 0; i < 4; i++) {
            int idx = t + i * 256;              // 0..1023
            int n   = idx >> 3;                 // tile row 0..127
            int kq  = idx & 7;                  // float4 group 0..7
            uint32_t doff = (uint32_t)(n * SSTRIDE + kq * 4) * 4;
            int grow = row0 + n;
            const float* asrc = x + (size_t)grow * IN_F + c * KCH + kq * 4;
            int asz = (grow < n_nodes) ? 16 : 0;
            CP_ASYNC16G(aBase + doff, asrc, asz);
            const float* bsrc = g_Wt + n * IN_F + c * KCH + kq * 4;
            CP_ASYNC16(bBase + doff, bsrc);
        }
        CP_COMMIT();
    };

    issue(0, 0);

    for (int c = 0; c < NCH; c++) {
        const int cur = c & 1;
        if (c + 1 < NCH) {
            issue(c + 1, cur ^ 1);
            CP_WAIT(1);
        } else {
            CP_WAIT(0);
        }
        __syncthreads();                 // chunk c data visible to all warps

        const float* As = (const float*)(smem + (size_t)cur * STAGE_BYTES);
        const float* Bs = (const float*)(smem + (size_t)cur * STAGE_BYTES + HALF_STAGE);

#pragma unroll
        for (int ks = 0; ks < KCH / 8; ks++) {   // 4 K8 steps
            uint32_t a[2][4];
#pragma unroll
            for (int mt = 0; mt < 2; mt++) {
                int r0 = wm + mt * 16 + gid;
                int kc = ks * 8 + tig;
                a[mt][0] = f2tf32(As[r0 * SSTRIDE + kc]);
                a[mt][1] = f2tf32(As[(r0 + 8) * SSTRIDE + kc]);
                a[mt][2] = f2tf32(As[r0 * SSTRIDE + kc + 4]);
                a[mt][3] = f2tf32(As[(r0 + 8) * SSTRIDE + kc + 4]);
            }
#pragma unroll
            for (int ng = 0; ng < 8; ng++) {
                int nr = wn + ng * 8 + gid;
                int kc = ks * 8 + tig;
                uint32_t b0 = __float_as_uint(Bs[nr * SSTRIDE + kc]);
                uint32_t b1 = __float_as_uint(Bs[nr * SSTRIDE + kc + 4]);
                mma_tf32(acc[0][ng], a[0], b0, b1);
                mma_tf32(acc[1][ng], a[1], b0, b1);
            }
        }
        __syncthreads();                 // all warps done before stage reuse
    }

    // ---- epilogue: bias + fp16 store (C frag: rows gid/gid+8, cols 2*tig) ----
#pragma unroll
    for (int nt = 0; nt < 8; nt++) {
        int col = wn + nt * 8 + 2 * tig;
        float2 bb = *(const float2*)(b + col);
#pragma unroll
        for (int mt = 0; mt < 2; mt++) {
            int r0g = row0 + wm + mt * 16 + gid;
            if (r0g < n_nodes) {
                __half2 h0 = __floats2half2_rn(acc[mt][nt][0] + bb.x,
                                               acc[mt][nt][1] + bb.y);
                *(__half2*)(g_support_h + (size_t)r0g * HID + col) = h0;
            }
            int r1g = r0g + 8;
            if (r1g < n_nodes) {
                __half2 h1 = __floats2half2_rn(acc[mt][nt][2] + bb.x,
                                               acc[mt][nt][3] + bb.y);
                *(__half2*)(g_support_h + (size_t)r1g * HID + col) = h1;
            }
        }
    }
}

// ---------------------------------------------------------------------------
// hist: int4-vectorized edge histogram (4 edges/thread)
// ---------------------------------------------------------------------------
__global__ __launch_bounds__(256) void hist_kernel(
    const int* __restrict__ adj_row, int n_edges)
{
    int base = (blockIdx.x * blockDim.x + threadIdx.x) * 4;
    if (base + 3 < n_edges) {
        int4 r = *(const int4*)(adj_row + base);
        atomicAdd(&g_cnt[r.x], 1);
        atomicAdd(&g_cnt[r.y], 1);
        atomicAdd(&g_cnt[r.z], 1);
        atomicAdd(&g_cnt[r.w], 1);
    } else {
        for (int e = base; e < n_edges; e++)
            atomicAdd(&g_cnt[adj_row[e]], 1);
    }
}

// scan_a: per-block reduce of g_cnt (256/block) -> g_bsum
__global__ __launch_bounds__(SCAN_B) void scan_a_kernel(int n_nodes)
{
    __shared__ int sm[SCAN_B / 32];
    const int t   = threadIdx.x;
    const int idx = blockIdx.x * SCAN_B + t;
    int v = (idx < n_nodes) ? g_cnt[idx] : 0;
#pragma unroll
    for (int o = 16; o > 0; o >>= 1) v += __shfl_down_sync(0xffffffffu, v, o);
    if ((t & 31) == 0) sm[t >> 5] = v;
    __syncthreads();
    if (t < 32) {
        int s = (t < SCAN_B / 32) ? sm[t] : 0;
#pragma unroll
        for (int o = 4; o > 0; o >>= 1) s += __shfl_down_sync(0xffffffffu, s, o);
        if (t == 0) g_bsum[blockIdx.x] = s;
    }
}

// scan_c: block prefix from g_bsum + local scan; re-zeroes g_cnt.
__global__ __launch_bounds__(SCAN_B) void scan_c_kernel(int n_sb, int n_nodes)
{
    __shared__ int bs[SCAN_B];
    __shared__ int sm[SCAN_B];
    const int t   = threadIdx.x;
    const int idx = blockIdx.x * SCAN_B + t;

    int bv = (t < n_sb) ? g_bsum[t] : 0;
    bs[t] = bv;
    __syncthreads();
#pragma unroll
    for (int o = 1; o < SCAN_B; o <<= 1) {
        int u = (t >= o) ? bs[t - o] : 0;
        __syncthreads();
        bs[t] += u;
        __syncthreads();
    }
    const int blk_prefix = (blockIdx.x > 0) ? bs[blockIdx.x - 1] : 0;
    if (blockIdx.x == 0 && t == 0) g_row_start[n_nodes] = bs[n_sb - 1];

    int v = (idx < n_nodes) ? g_cnt[idx] : 0;
    sm[t] = v;
    __syncthreads();
#pragma unroll
    for (int o = 1; o < SCAN_B; o <<= 1) {
        int u = (t >= o) ? sm[t - o] : 0;
        __syncthreads();
        sm[t] += u;
        __syncthreads();
    }
    if (idx < n_nodes) {
        int excl = blk_prefix + sm[t] - v;
        g_row_start[idx] = excl;
        g_cursor[idx]    = excl;
        g_cnt[idx]       = 0;
    }
}

// fill: int4-vectorized (4 edges/thread, independent atomic chains)
__global__ __launch_bounds__(256) void fill_kernel(
    const int*   __restrict__ adj_row,
    const int*   __restrict__ adj_col,
    const float* __restrict__ adj_val,
    int n_edges)
{
    int base = (blockIdx.x * blockDim.x + threadIdx.x) * 4;
    if (base + 3 < n_edges) {
        int4   r = *(const int4*)(adj_row + base);
        int4   c = *(const int4*)(adj_col + base);
        float4 v = *(const float4*)(adj_val + base);
        int p0 = atomicAdd(&g_cursor[r.x], 1);
        int p1 = atomicAdd(&g_cursor[r.y], 1);
        int p2 = atomicAdd(&g_cursor[r.z], 1);
        int p3 = atomicAdd(&g_cursor[r.w], 1);
        g_edge[p0] = make_int2(c.x, __float_as_int(v.x));
        g_edge[p1] = make_int2(c.y, __float_as_int(v.y));
        g_edge[p2] = make_int2(c.z, __float_as_int(v.z));
        g_edge[p3] = make_int2(c.w, __float_as_int(v.w));
    } else {
        for (int e = base; e < n_edges; e++) {
            int r   = adj_row[e];
            int pos = atomicAdd(&g_cursor[r], 1);
            g_edge[pos] = make_int2(adj_col[e], __float_as_int(adj_val[e]));
        }
    }
}

// ---------------------------------------------------------------------------
// gather: warp per row, half-warp per edge (16 lanes x uint4 = 256B row),
// shfl_xor(16) merge, no atomics.
// ---------------------------------------------------------------------------
__global__ __launch_bounds__(256) void row_gather_kernel(
    float* __restrict__ out, int n_nodes)
{
    const int row  = (blockIdx.x * blockDim.x + threadIdx.x) >> 5;
    const int lane = threadIdx.x & 31;
    const int half = lane >> 4;
    const int hl   = lane & 15;
    if (row >= n_nodes) return;

    const int s0 = g_row_start[row];
    const int s1 = g_row_start[row + 1];

    const uint4* sup = reinterpret_cast<const uint4*>(g_support_h);
    float acc[8];
#pragma unroll
    for (int j = 0; j < 8; j++) acc[j] = 0.0f;

    int e = s0 + half;
    for (; e + 2 < s1; e += 4) {
        int2 ev0 = g_edge[e];
        int2 ev1 = g_edge[e + 2];
        uint4 r0 = sup[(size_t)ev0.x * 16 + hl];
        uint4 r1 = sup[(size_t)ev1.x * 16 + hl];
        float v0 = __int_as_float(ev0.y);
        float v1 = __int_as_float(ev1.y);
        float2 p0 = __half22float2(*(const __half2*)&r0.x);
        float2 p1 = __half22float2(*(const __half2*)&r0.y);
        float2 p2 = __half22float2(*(const __half2*)&r0.z);
        float2 p3 = __half22float2(*(const __half2*)&r0.w);
        float2 q0 = __half22float2(*(const __half2*)&r1.x);
        float2 q1 = __half22float2(*(const __half2*)&r1.y);
        float2 q2 = __half22float2(*(const __half2*)&r1.z);
        float2 q3 = __half22float2(*(const __half2*)&r1.w);
        acc[0] += v0 * p0.x + v1 * q0.x;
        acc[1] += v0 * p0.y + v1 * q0.y;
        acc[2] += v0 * p1.x + v1 * q1.x;
        acc[3] += v0 * p1.y + v1 * q1.y;
        acc[4] += v0 * p2.x + v1 * q2.x;
        acc[5] += v0 * p2.y + v1 * q2.y;
        acc[6] += v0 * p3.x + v1 * q3.x;
        acc[7] += v0 * p3.y + v1 * q3.y;
    }
    for (; e < s1; e += 2) {
        int2 ev = g_edge[e];
        uint4 r0 = sup[(size_t)ev.x * 16 + hl];
        float v = __int_as_float(ev.y);
        float2 p0 = __half22float2(*(const __half2*)&r0.x);
        float2 p1 = __half22float2(*(const __half2*)&r0.y);
        float2 p2 = __half22float2(*(const __half2*)&r0.z);
        float2 p3 = __half22float2(*(const __half2*)&r0.w);
        acc[0] += v * p0.x; acc[1] += v * p0.y;
        acc[2] += v * p1.x; acc[3] += v * p1.y;
        acc[4] += v * p2.x; acc[5] += v * p2.y;
        acc[6] += v * p3.x; acc[7] += v * p3.y;
    }

#pragma unroll
    for (int j = 0; j < 8; j++)
        acc[j] += __shfl_xor_sync(0xffffffffu, acc[j], 16);

    if (half == 0) {
        float4* o = reinterpret_cast<float4*>(out + (size_t)row * HID + hl * 8);
        o[0] = make_float4(acc[0], acc[1], acc[2], acc[3]);
        o[1] = make_float4(acc[4], acc[5], acc[6], acc[7]);
    }
}

// ---------------------------------------------------------------------------
// Side stream + events, created ONCE (no device-mem allocation APIs).
// ---------------------------------------------------------------------------
struct AuxStreams {
    cudaStream_t s  = nullptr;
    cudaEvent_t  e1 = nullptr, e2 = nullptr;
    bool ok = false;
    AuxStreams() {
        if (cudaStreamCreateWithFlags(&s, cudaStreamNonBlocking) != cudaSuccess) { s = nullptr; return; }
        if (cudaEventCreateWithFlags(&e1, cudaEventDisableTiming) != cudaSuccess) { e1 = nullptr; return; }
        if (cudaEventCreateWithFlags(&e2, cudaEventDisableTiming) != cudaSuccess) { e2 = nullptr; return; }
        ok = true;
    }
};
static AuxStreams g_aux;

// ---------------------------------------------------------------------------
// Launch: inputs: x, adj_row, adj_col, adj_val, W, b
// Graph:  main: wtf32 -> gemm ----------------.-> gather
//         side: hist -> scan_a -> scan_c -> fill'
// ---------------------------------------------------------------------------
extern "C" void kernel_launch(void* const* d_in, const int* in_sizes, int n_in,
                              void* d_out, int out_size)
{
    const float* x       = (const float*)d_in[0];
    const int*   adj_row = (const int*)  d_in[1];
    const int*   adj_col = (const int*)  d_in[2];
    const float* adj_val = (const float*)d_in[3];
    const float* W       = (const float*)d_in[4];
    const float* b       = (const float*)d_in[5];
    float*       out     = (float*)d_out;

    const int n_nodes = in_sizes[0] / IN_F;
    const int n_edges = in_sizes[1];
    const int n_sb    = (n_nodes + SCAN_B - 1) / SCAN_B;
    const int gemm_blocks = (n_nodes + TILE_M - 1) / TILE_M;

    cudaFuncSetAttribute(gcn_linear_tf32_kernel,
                         cudaFuncAttributeMaxDynamicSharedMemorySize, GEMM_SMEM);

    const bool par = g_aux.ok;
    cudaStream_t sbin = par ? g_aux.s : (cudaStream_t)0;

    if (par) {
        cudaEventRecord(g_aux.e1, 0);
        cudaStreamWaitEvent(sbin, g_aux.e1, 0);
    }

    wtf32_kernel<<<32, 256>>>(W);
    gcn_linear_tf32_kernel<<<gemm_blocks, 256, GEMM_SMEM>>>(x, b, n_nodes);

    hist_kernel<<<(n_edges / 4 + 255) / 256, 256, 0, sbin>>>(adj_row, n_edges);
    scan_a_kernel<<<n_sb, SCAN_B, 0, sbin>>>(n_nodes);
    scan_c_kernel<<<n_sb, SCAN_B, 0, sbin>>>(n_sb, n_nodes);
    fill_kernel<<<(n_edges / 4 + 255) / 256, 256, 0, sbin>>>(adj_row, adj_col, adj_val, n_edges);

    if (par) {
        cudaEventRecord(g_aux.e2, sbin);
        cudaStreamWaitEvent(0, g_aux.e2, 0);
    }

    row_gather_kernel<<<(n_nodes * 32 + 255) / 256, 256>>>(out, n_nodes);
}